// round 7
// baseline (speedup 1.0000x reference)
#include <cuda_runtime.h>
#include <cuda_fp16.h>
#include <math.h>

namespace {
constexpr int B_ = 128, S_ = 128, E_ = 256, D_ = 256, O_ = 64;
constexpr int NT = 512;

// dynamic smem layout (bytes)
constexpr int OFF_X16  = 0;       // half [2][128][256] = 131072
constexpr int OFF_GS   = 131072;  // float[2][4][1024]  =  32768
constexpr int OFF_PART = 163840;  // float[2048]        =   8192
constexpr int OFF_H    = 172032;  // float[2][256]
constexpr int OFF_C    = 174080;
constexpr int OFF_HC   = 176128;
constexpr int OFF_CTX  = 178176;
constexpr int OFF_GB   = 180224;  // float[1024]
constexpr int OFF_SC   = 184320;  // float[2][128]
constexpr int OFF_Y    = 185344;  // float[2][64]
constexpr int OFF_YT   = 185856;  // float[2][64]
constexpr int OFF_W2   = 186368;  // float[256]
constexpr int OFF_FCB  = 187392;  // float[64]
constexpr int SMEM_BYTES = 187648;
}

// fp16 weight copies + enc_proj (converted/computed once per launch)
__device__ __half2 g_whc[D_ * E_];          // (Wh, Wc) interleaved
__device__ __half  g_whh[D_ * 4 * D_];      // [256][1024]
__device__ __half  g_wih[O_ * 4 * D_];      // [64][1024]
__device__ __half  g_fcwT[O_ * (E_ + O_)];  // [64 cols][320 rows]
__device__ __half  g_ep16[B_ * S_ * E_];    // enc_proj, fp16
__device__ float   g_hctx[B_ * (D_ + E_)];

__device__ __forceinline__ float sigm_f(float x) {
    float e = __expf(-x);
    return __fdividef(1.f, 1.f + e);
}
__device__ __forceinline__ float tanh_f(float x) {
    float e = __expf(2.f * x);
    return 1.f - __fdividef(2.f, e + 1.f);
}
__device__ __forceinline__ float tanh_a(float x) {
    float y;
    asm("tanh.approx.f32 %0, %1;" : "=f"(y) : "f"(x));
    return y;
}
__device__ __forceinline__ void barA() { asm volatile("bar.sync 1, 256;" ::: "memory"); }
__device__ __forceinline__ void bsync(int id) {
    asm volatile("bar.sync %0, 512;" :: "r"(id) : "memory");
}
__device__ __forceinline__ void barrive(int id) {
    asm volatile("bar.arrive %0, 512;" :: "r"(id) : "memory");
}

__global__ void __launch_bounds__(256) convert_weights_kernel(
    const float* __restrict__ W1, const float* __restrict__ Whh,
    const float* __restrict__ Wih, const float* __restrict__ fcW)
{
    int i = blockIdx.x * 256 + threadIdx.x;
    if (i < D_ * E_) {
        int d = i >> 8, c = i & 255;
        g_whc[i] = __floats2half2_rn(W1[d * E_ + c], W1[(D_ + d) * E_ + c]);
    }
    if (i < D_ * 4 * D_)    g_whh[i] = __float2half_rn(Whh[i]);
    if (i < O_ * 4 * D_)    g_wih[i] = __float2half_rn(Wih[i]);
    if (i < O_ * (E_ + O_)) {
        int c = i / 320, k = i % 320;
        g_fcwT[i] = __float2half_rn(fcW[k * 64 + c]);
    }
}

// enc_proj = x[b] @ We -> g_ep16 (one CTA per batch, chip-wide)
__global__ void __launch_bounds__(512) encproj_kernel(
    const float* __restrict__ x, const float* __restrict__ W1)
{
    extern __shared__ char sm[];
    __half* xs = (__half*)sm;   // [128][256]
    const int b = blockIdx.x, t = threadIdx.x;
    const int r = t >> 6, j = t & 63;

    const float* xb = x + (size_t)b * S_ * E_;
    for (int i = t; i < S_ * E_; i += 512) xs[i] = __float2half_rn(xb[i]);
    __syncthreads();

    const float4* We4 = (const float4*)(W1 + 2 * D_ * E_);
    __half* epb = g_ep16 + (size_t)b * S_ * E_;
    for (int s0 = 16 * r; s0 < 16 * r + 16; s0 += 8) {
        float4 acc[8];
        #pragma unroll
        for (int q = 0; q < 8; q++) acc[q] = make_float4(0.f, 0.f, 0.f, 0.f);
        for (int e = 0; e < E_; e++) {
            float4 wv = We4[e * 64 + j];
            #pragma unroll
            for (int q = 0; q < 8; q++) {
                float xv = __half2float(xs[(s0 + q) * E_ + e]);
                acc[q].x = fmaf(xv, wv.x, acc[q].x);
                acc[q].y = fmaf(xv, wv.y, acc[q].y);
                acc[q].z = fmaf(xv, wv.z, acc[q].z);
                acc[q].w = fmaf(xv, wv.w, acc[q].w);
            }
        }
        #pragma unroll
        for (int q = 0; q < 8; q++) {
            __half2* rowp = (__half2*)(epb + (size_t)(s0 + q) * E_);
            rowp[2 * j]     = __floats2half2_rn(acc[q].x, acc[q].y);
            rowp[2 * j + 1] = __floats2half2_rn(acc[q].z, acc[q].w);
        }
    }
}

__global__ void __launch_bounds__(NT, 1) attn_decoder_kernel(
    const float* __restrict__ x, const float* __restrict__ yh,
    const float* __restrict__ h0, const float* __restrict__ c0,
    const float* __restrict__ b1, const float* __restrict__ w2,
    const float* __restrict__ b2, const float* __restrict__ bih,
    const float* __restrict__ bhh, const float* __restrict__ fcb)
{
    extern __shared__ char smraw[];
    __half* x16  = (__half*)(smraw + OFF_X16);   // [2][128][256]
    float*  gsm  = (float*)(smraw + OFF_GS);     // [2][4][1024]
    float*  part = (float*)(smraw + OFF_PART);   // [2048] scratch
    float*  hsm  = (float*)(smraw + OFF_H);      // [2][256]
    float*  csm  = (float*)(smraw + OFF_C);
    float*  hcsm = (float*)(smraw + OFF_HC);
    float*  ctxs = (float*)(smraw + OFF_CTX);
    float*  gb   = (float*)(smraw + OFF_GB);     // [1024]
    float*  sc   = (float*)(smraw + OFF_SC);     // [2][128]
    float*  ysm  = (float*)(smraw + OFF_Y);      // [2][64]
    float*  ytl  = (float*)(smraw + OFF_YT);     // [2][64]
    float*  w2s  = (float*)(smraw + OFF_W2);
    float*  fcbs = (float*)(smraw + OFF_FCB);

    const int b0   = 2 * blockIdx.x;
    const int t    = threadIdx.x;
    const int lane = t & 31, w = t >> 5;

    // ---- prologue (all 512) ----
    for (int i = t; i < 2 * S_ * E_; i += NT) {
        int bt = i >> 15, off = i & 32767;
        x16[i] = __float2half_rn(x[((size_t)(b0 + bt)) * S_ * E_ + off]);
    }
    {
        int bt = t >> 8, d = t & 255;
        hsm[bt * 256 + d] = h0[(b0 + bt) * D_ + d];
        csm[bt * 256 + d] = c0[(b0 + bt) * D_ + d];
    }
    float rb1 = 0.f;
    if (t < 256) {
        w2s[t] = w2[t];
        rb1 = b1[t];
        float4 a  = ((const float4*)bih)[t];
        float4 c4 = ((const float4*)bhh)[t];
        ((float4*)gb)[t] = make_float4(a.x + c4.x, a.y + c4.y, a.z + c4.z, a.w + c4.w);
        if (t < O_) fcbs[t] = fcb[t];
    }
    const float b2c = b2[0];
    __syncthreads();

    const uint4* whc4 = (const uint4*)g_whc;
    const uint4* whh4 = (const uint4*)g_whh;
    const uint4* wih4 = (const uint4*)g_wih;

    if (t < 256) {
        // ==================== GROUP A: compute chain ====================
        float w2r[8];
        *(float4*)&w2r[0] = *(float4*)(w2s + 8 * lane);
        *(float4*)&w2r[4] = *(float4*)(w2s + 8 * lane + 4);
        const __half* ep0 = g_ep16 + (size_t)b0 * S_ * E_;
        const __half* ep1 = ep0 + S_ * E_;

        barrive(5);   // h0/c0 ready for B's first step
        for (int step = 0; step < S_; step++) {
            bsync(3);   // hc partials ready
            // hc reduce (both batches) + ysm prefetch
            {
                float v0 = rb1 + part[t] + part[256 + t] + part[512 + t] + part[768 + t];
                float v1 = rb1 + part[1024 + t] + part[1280 + t] + part[1536 + t] + part[1792 + t];
                hcsm[t] = v0;
                hcsm[256 + t] = v1;
                if (t < 128) {
                    int bt = t >> 6, c = t & 63;
                    ysm[bt * 64 + c] = yh[((size_t)(b0 + bt) * S_ + step) * O_ + c];
                }
            }
            barA();

            // scores: warp w handles s = 16w..16w+15, both batches
            {
                float hcr[2][8];
                *(float4*)&hcr[0][0] = *(float4*)(hcsm + 8 * lane);
                *(float4*)&hcr[0][4] = *(float4*)(hcsm + 8 * lane + 4);
                *(float4*)&hcr[1][0] = *(float4*)(hcsm + 256 + 8 * lane);
                *(float4*)&hcr[1][4] = *(float4*)(hcsm + 256 + 8 * lane + 4);

                int s = 16 * w;
                const __half* r0 = ep0 + (s << 8) + 8 * lane;
                const __half* r1 = ep1 + (s << 8) + 8 * lane;
                uint4 u0 = *(const uint4*)r0;
                uint4 u1 = *(const uint4*)r1;
                for (int si = 0; si < 16; si++) {
                    uint4 n0, n1;
                    if (si < 15) {
                        n0 = *(const uint4*)(r0 + 256);
                        n1 = *(const uint4*)(r1 + 256);
                    }
                    float s0 = 0.f, s1 = 0.f;
                    #pragma unroll
                    for (int k = 0; k < 4; k++) {
                        float2 p0 = __half22float2(((const __half2*)&u0)[k]);
                        float2 p1 = __half22float2(((const __half2*)&u1)[k]);
                        s0 = fmaf(tanh_a(p0.x + hcr[0][2 * k]),     w2r[2 * k],     s0);
                        s0 = fmaf(tanh_a(p0.y + hcr[0][2 * k + 1]), w2r[2 * k + 1], s0);
                        s1 = fmaf(tanh_a(p1.x + hcr[1][2 * k]),     w2r[2 * k],     s1);
                        s1 = fmaf(tanh_a(p1.y + hcr[1][2 * k + 1]), w2r[2 * k + 1], s1);
                    }
                    #pragma unroll
                    for (int off = 16; off; off >>= 1) {
                        s0 += __shfl_xor_sync(0xffffffffu, s0, off);
                        s1 += __shfl_xor_sync(0xffffffffu, s1, off);
                    }
                    if (lane == 0) {
                        sc[16 * w + si]       = s0 + b2c;
                        sc[128 + 16 * w + si] = s1 + b2c;
                    }
                    u0 = n0; u1 = n1; r0 += 256; r1 += 256;
                }
            }
            barA();

            // softmax: warp 0 -> batch0, warp 1 -> batch1
            if (w < 2) {
                float* scb = sc + w * 128;
                float v0 = scb[lane], v1 = scb[32 + lane], v2 = scb[64 + lane], v3 = scb[96 + lane];
                float m = fmaxf(fmaxf(v0, v1), fmaxf(v2, v3));
                #pragma unroll
                for (int off = 16; off; off >>= 1)
                    m = fmaxf(m, __shfl_xor_sync(0xffffffffu, m, off));
                float e0 = __expf(v0 - m), e1 = __expf(v1 - m);
                float e2 = __expf(v2 - m), e3 = __expf(v3 - m);
                float s2 = e0 + e1 + e2 + e3;
                #pragma unroll
                for (int off = 16; off; off >>= 1)
                    s2 += __shfl_xor_sync(0xffffffffu, s2, off);
                float inv = __fdividef(1.f, s2);
                scb[lane]      = e0 * inv;
                scb[32 + lane] = e1 * inv;
                scb[64 + lane] = e2 * inv;
                scb[96 + lane] = e3 * inv;
            }
            barA();

            // context partials: (bt = t>>7, sq = (t>>5)&3, c32 = t&31)
            {
                const int c32 = t & 31, sq = (t >> 5) & 3, bt = t >> 7;
                const __half* xb16 = x16 + bt * (S_ * E_);
                const float*  scb  = sc + bt * 128;
                float acc[8];
                #pragma unroll
                for (int i = 0; i < 8; i++) acc[i] = 0.f;
                const int s0 = 32 * sq;
                #pragma unroll 4
                for (int s = s0; s < s0 + 32; s++) {
                    uint4 xv = ((const uint4*)(xb16 + (s << 8)))[c32];
                    float al = scb[s];
                    #pragma unroll
                    for (int k = 0; k < 4; k++) {
                        float2 p = __half22float2(((const __half2*)&xv)[k]);
                        acc[2 * k]     = fmaf(al, p.x, acc[2 * k]);
                        acc[2 * k + 1] = fmaf(al, p.y, acc[2 * k + 1]);
                    }
                }
                float* dst = part + bt * 1024 + sq * 256 + 8 * c32;
                ((float4*)dst)[0] = make_float4(acc[0], acc[1], acc[2], acc[3]);
                ((float4*)dst)[1] = make_float4(acc[4], acc[5], acc[6], acc[7]);
            }
            barA();
            {
                const int bt = t >> 7, e2 = t & 127;
                const float2* pp = (const float2*)(part + bt * 1024);
                float2 c0v = pp[e2], c1v = pp[128 + e2], c2v = pp[256 + e2], c3v = pp[384 + e2];
                ((float2*)(ctxs + bt * 256))[e2] =
                    make_float2(c0v.x + c1v.x + c2v.x + c3v.x,
                                c0v.y + c1v.y + c2v.y + c3v.y);
            }
            barA();

            // y_tilde partials: (bt = t>>7, rA = (t>>6)&1, jc = t&63)
            {
                const int bt = t >> 7, rA = (t >> 6) & 1, jc = t & 63;
                const uint4* fw = (const uint4*)(g_fcwT + jc * 320) + 20 * rA;
                const float* cb = ctxs + bt * 256;
                const float* yb = ysm + bt * 64;
                float acc = 0.f;
                #pragma unroll 4
                for (int u = 0; u < 20; u++) {
                    uint4 v = fw[u];
                    int kb = 160 * rA + 8 * u;
                    #pragma unroll
                    for (int q = 0; q < 4; q++) {
                        float2 p = __half22float2(((const __half2*)&v)[q]);
                        int k = kb + 2 * q;
                        float a0 = (k     < E_) ? cb[k]     : yb[k - E_];
                        float a1 = (k + 1 < E_) ? cb[k + 1] : yb[k + 1 - E_];
                        acc = fmaf(a0, p.x, fmaf(a1, p.y, acc));
                    }
                }
                part[t] = acc;
            }
            barA();
            if (t < 128) {
                int bt = t >> 6, c = t & 63;
                ytl[bt * 64 + c] = fcbs[c] + part[bt * 128 + c] + part[bt * 128 + 64 + c];
            }
            barrive(6);   // ytl ready for B's wih stream

            bsync(4);     // gate partials ready
            #pragma unroll
            for (int bt = 0; bt < 2; bt++) {
                const float* g = gsm + bt * 4096;
                float gi = g[t]       + g[1024 + t]       + g[2048 + t]       + g[3072 + t]       + gb[t];
                float gf = g[256 + t] + g[1024 + 256 + t] + g[2048 + 256 + t] + g[3072 + 256 + t] + gb[256 + t];
                float gg = g[512 + t] + g[1024 + 512 + t] + g[2048 + 512 + t] + g[3072 + 512 + t] + gb[512 + t];
                float go = g[768 + t] + g[1024 + 768 + t] + g[2048 + 768 + t] + g[3072 + 768 + t] + gb[768 + t];
                float cv = csm[bt * 256 + t];
                float cn = fmaf(sigm_f(gf), cv, sigm_f(gi) * tanh_f(gg));
                float hn = sigm_f(go) * tanh_f(cn);
                hsm[bt * 256 + t] = hn;
                csm[bt * 256 + t] = cn;
            }
            barrive(5);   // new h,c ready for B
        }

        #pragma unroll
        for (int bt = 0; bt < 2; bt++) {
            g_hctx[(b0 + bt) * 512 + t]       = hsm[bt * 256 + t];
            g_hctx[(b0 + bt) * 512 + 256 + t] = ctxs[bt * 256 + t];
        }
    } else {
        // ==================== GROUP B: weight streamer ====================
        const int tb  = t - 256;
        const int r2  = tb >> 6, jb = tb & 63;      // whc mapping
        const int khB = tb >> 7, c8 = tb & 127;     // whh/wih mapping

        for (int step = 0; step < S_; step++) {
            bsync(5);   // wait h,c

            // ---- hc partials: rows 64r2.., cols 4jb.., both batches ----
            {
                float a0[4], a1[4];
                #pragma unroll
                for (int i = 0; i < 4; i++) { a0[i] = 0.f; a1[i] = 0.f; }
                const int d0 = 64 * r2;
                #pragma unroll
                for (int kk = 0; kk < 64; kk += 8) {
                    uint4 v[8];
                    #pragma unroll
                    for (int q = 0; q < 8; q++) v[q] = whc4[(d0 + kk + q) * 64 + jb];
                    #pragma unroll
                    for (int q = 0; q < 8; q++) {
                        int d = d0 + kk + q;
                        float h0v = hsm[d], c0v = csm[d];
                        float h1v = hsm[256 + d], c1v = csm[256 + d];
                        #pragma unroll
                        for (int k = 0; k < 4; k++) {
                            float2 p = __half22float2(((const __half2*)&v[q])[k]);
                            a0[k] = fmaf(h0v, p.x, fmaf(c0v, p.y, a0[k]));
                            a1[k] = fmaf(h1v, p.x, fmaf(c1v, p.y, a1[k]));
                        }
                    }
                }
                ((float4*)(part + r2 * 256))[jb]        = make_float4(a0[0], a0[1], a0[2], a0[3]);
                ((float4*)(part + 1024 + r2 * 256))[jb] = make_float4(a1[0], a1[1], a1[2], a1[3]);
            }
            barrive(3);

            // ---- gh = h @ Whh : k-half khB, cols 8c8.., both batches ----
            {
                float a0[8], a1[8];
                #pragma unroll
                for (int i = 0; i < 8; i++) { a0[i] = 0.f; a1[i] = 0.f; }
                const int base = 128 * khB;
                #pragma unroll 2
                for (int k0 = 0; k0 < 128; k0 += 8) {
                    uint4 v[8];
                    #pragma unroll
                    for (int q = 0; q < 8; q++) v[q] = whh4[(base + k0 + q) * 128 + c8];
                    #pragma unroll
                    for (int q = 0; q < 8; q++) {
                        float h0v = hsm[base + k0 + q];
                        float h1v = hsm[256 + base + k0 + q];
                        #pragma unroll
                        for (int k = 0; k < 4; k++) {
                            float2 p = __half22float2(((const __half2*)&v[q])[k]);
                            a0[2 * k]     = fmaf(h0v, p.x, a0[2 * k]);
                            a0[2 * k + 1] = fmaf(h0v, p.y, a0[2 * k + 1]);
                            a1[2 * k]     = fmaf(h1v, p.x, a1[2 * k]);
                            a1[2 * k + 1] = fmaf(h1v, p.y, a1[2 * k + 1]);
                        }
                    }
                }
                float* d0p = gsm + khB * 1024 + 8 * c8;
                float* d1p = gsm + 4096 + khB * 1024 + 8 * c8;
                ((float4*)d0p)[0] = make_float4(a0[0], a0[1], a0[2], a0[3]);
                ((float4*)d0p)[1] = make_float4(a0[4], a0[5], a0[6], a0[7]);
                ((float4*)d1p)[0] = make_float4(a1[0], a1[1], a1[2], a1[3]);
                ((float4*)d1p)[1] = make_float4(a1[4], a1[5], a1[6], a1[7]);
            }

            bsync(6);   // wait ytl

            // ---- gih = ytl @ Wih : rows 32khB.., cols 8c8.., both batches ----
            {
                float a0[8], a1[8];
                #pragma unroll
                for (int i = 0; i < 8; i++) { a0[i] = 0.f; a1[i] = 0.f; }
                const int k0b = 32 * khB;
                #pragma unroll
                for (int kk = 0; kk < 32; kk += 8) {
                    uint4 v[8];
                    #pragma unroll
                    for (int q = 0; q < 8; q++) v[q] = wih4[(k0b + kk + q) * 128 + c8];
                    #pragma unroll
                    for (int q = 0; q < 8; q++) {
                        float y0v = ytl[k0b + kk + q];
                        float y1v = ytl[64 + k0b + kk + q];
                        #pragma unroll
                        for (int k = 0; k < 4; k++) {
                            float2 p = __half22float2(((const __half2*)&v[q])[k]);
                            a0[2 * k]     = fmaf(y0v, p.x, a0[2 * k]);
                            a0[2 * k + 1] = fmaf(y0v, p.y, a0[2 * k + 1]);
                            a1[2 * k]     = fmaf(y1v, p.x, a1[2 * k]);
                            a1[2 * k + 1] = fmaf(y1v, p.y, a1[2 * k + 1]);
                        }
                    }
                }
                float* d0p = gsm + (2 + khB) * 1024 + 8 * c8;
                float* d1p = gsm + 4096 + (2 + khB) * 1024 + 8 * c8;
                ((float4*)d0p)[0] = make_float4(a0[0], a0[1], a0[2], a0[3]);
                ((float4*)d0p)[1] = make_float4(a0[4], a0[5], a0[6], a0[7]);
                ((float4*)d1p)[0] = make_float4(a1[0], a1[1], a1[2], a1[3]);
                ((float4*)d1p)[1] = make_float4(a1[4], a1[5], a1[6], a1[7]);
            }
            barrive(4);
        }
    }
}

// out[128, 8192] = g_hctx[128,512] @ fc_out_W[512,8192] + b ; 128 blocks, 64-col tiles
__global__ void __launch_bounds__(256, 1) fcout_kernel(
    const float* __restrict__ W, const float* __restrict__ bias,
    float* __restrict__ out)
{
    __shared__ float As[32][128];
    __shared__ float Ws[32][64];
    const int n0 = blockIdx.x * 64;
    const int t  = threadIdx.x;
    const int tx = t & 7, ty = t >> 3;

    float bv[8];
    #pragma unroll
    for (int jj = 0; jj < 8; jj++) bv[jj] = bias[n0 + 8 * tx + jj];

    float acc[4][8];
    #pragma unroll
    for (int i = 0; i < 4; i++)
        #pragma unroll
        for (int jj = 0; jj < 8; jj++) acc[i][jj] = 0.f;

    for (int k0 = 0; k0 < 512; k0 += 32) {
        {
            int q    = t & 7;
            int row0 = t >> 3;
            #pragma unroll
            for (int i = 0; i < 4; i++) {
                int rr = row0 + 32 * i;
                float4 v = *(const float4*)(g_hctx + rr * 512 + k0 + 4 * q);
                As[4 * q + 0][rr] = v.x;
                As[4 * q + 1][rr] = v.y;
                As[4 * q + 2][rr] = v.z;
                As[4 * q + 3][rr] = v.w;
            }
            int nq  = t & 15;
            int kk0 = t >> 4;
            #pragma unroll
            for (int i = 0; i < 2; i++) {
                int kk = kk0 + 16 * i;
                float4 v = *(const float4*)(W + (size_t)(k0 + kk) * 8192 + n0 + 4 * nq);
                *(float4*)(&Ws[kk][4 * nq]) = v;
            }
        }
        __syncthreads();
        #pragma unroll 8
        for (int kk = 0; kk < 32; kk++) {
            float a[4], wv[8];
            #pragma unroll
            for (int i = 0; i < 4; i++) a[i] = As[kk][4 * ty + i];
            #pragma unroll
            for (int jj = 0; jj < 8; jj++) wv[jj] = Ws[kk][8 * tx + jj];
            #pragma unroll
            for (int i = 0; i < 4; i++)
                #pragma unroll
                for (int jj = 0; jj < 8; jj++)
                    acc[i][jj] = fmaf(a[i], wv[jj], acc[i][jj]);
        }
        __syncthreads();
    }
    #pragma unroll
    for (int i = 0; i < 4; i++) {
        int bb = 4 * ty + i;
        #pragma unroll
        for (int jj = 0; jj < 8; jj++)
            out[(size_t)bb * 8192 + n0 + 8 * tx + jj] = acc[i][jj] + bv[jj];
    }
}

extern "C" void kernel_launch(void* const* d_in, const int* in_sizes, int n_in,
                              void* d_out, int out_size)
{
    const float* x   = (const float*)d_in[0];
    const float* yh  = (const float*)d_in[1];
    const float* h0  = (const float*)d_in[2];
    const float* c0  = (const float*)d_in[3];
    const float* W1  = (const float*)d_in[4];
    const float* b1  = (const float*)d_in[5];
    const float* w2  = (const float*)d_in[6];
    const float* b2  = (const float*)d_in[7];
    const float* Wih = (const float*)d_in[8];
    const float* Whh = (const float*)d_in[9];
    const float* bih = (const float*)d_in[10];
    const float* bhh = (const float*)d_in[11];
    const float* fcW = (const float*)d_in[12];
    const float* fcb = (const float*)d_in[13];
    const float* foW = (const float*)d_in[14];
    const float* fob = (const float*)d_in[15];

    convert_weights_kernel<<<(D_ * 4 * D_ + 255) / 256, 256>>>(W1, Whh, Wih, fcW);

    cudaFuncSetAttribute(encproj_kernel,
                         cudaFuncAttributeMaxDynamicSharedMemorySize, S_ * E_ * 2);
    encproj_kernel<<<B_, 512, S_ * E_ * 2>>>(x, W1);

    cudaFuncSetAttribute(attn_decoder_kernel,
                         cudaFuncAttributeMaxDynamicSharedMemorySize, SMEM_BYTES);
    attn_decoder_kernel<<<B_ / 2, NT, SMEM_BYTES>>>(x, yh, h0, c0, b1, w2, b2,
                                                    bih, bhh, fcb);
    fcout_kernel<<<128, 256>>>(foW, fob, (float*)d_out);
}

// round 8
// speedup vs baseline: 1.2204x; 1.2204x over previous
#include <cuda_runtime.h>
#include <cuda_fp16.h>
#include <math.h>

namespace {
constexpr int B_ = 128, S_ = 128, E_ = 256, D_ = 256, O_ = 64;
constexpr int NT = 512;
constexpr int NPAIR = B_ / 2;

// dynamic smem layout (bytes)
constexpr int OFF_EP   = 0;       // half [128][256] own-batch enc_proj  65536
constexpr int OFF_X16  = 65536;   // half [128][256] own-batch x         65536
constexpr int OFF_GS   = 131072;  // float[2][4][512] gate partials      16384
constexpr int OFF_PB   = 147456;  // float[2048] B scratch                8192
constexpr int OFF_PA   = 155648;  // float[768]  A scratch                3072
constexpr int OFF_H    = 158720;  // float[2][256]
constexpr int OFF_C    = 160768;  // float[2][256]
constexpr int OFF_HC   = 162816;  // float[256]
constexpr int OFF_HCP  = 163840;  // float[128]  local hc piece
constexpr int OFF_CTX  = 164352;  // float[256]
constexpr int OFF_GB   = 165376;  // float[1024]
constexpr int OFF_SC   = 169472;  // float[128]
constexpr int OFF_Y    = 169984;  // float[64]
constexpr int OFF_YT   = 170240;  // float[2][64]
constexpr int OFF_W2   = 170752;  // float[256]
constexpr int OFF_FCB  = 171776;  // float[64]
constexpr int SMEM_BYTES = 172032;
}

// fp16 weight copies (converted once per launch)
__device__ __half2 g_whc[D_ * E_];          // (Wh, Wc) interleaved
__device__ __half  g_whh[D_ * 4 * D_];      // [256][1024]
__device__ __half  g_wih[O_ * 4 * D_];      // [64][1024]
__device__ __half  g_fcwT[O_ * (E_ + O_)];  // [64 cols][320 rows]
__device__ float   g_hctx[B_ * (D_ + E_)];

// cross-CTA exchange buffers (pairwise, L2-resident)
__device__ float g_x1[NPAIR][2][128];  // hc piece for peer's batch
__device__ float g_x2[NPAIR][2][64];   // ytl of own batch
__device__ float g_x3[NPAIR][2][512];  // updated h,c halves [b][h/c][128]
__device__ int   g_flag[NPAIR][2][3][32];

__device__ __forceinline__ float sigm_f(float x) {
    float e = __expf(-x);
    return __fdividef(1.f, 1.f + e);
}
__device__ __forceinline__ float tanh_f(float x) {
    float e = __expf(2.f * x);
    return 1.f - __fdividef(2.f, e + 1.f);
}
__device__ __forceinline__ float tanh_a(float x) {
    float y;
    asm("tanh.approx.f32 %0, %1;" : "=f"(y) : "f"(x));
    return y;
}
__device__ __forceinline__ void barA()  { asm volatile("bar.sync 1, 256;" ::: "memory"); }
__device__ __forceinline__ void barB()  { asm volatile("bar.sync 2, 256;" ::: "memory"); }
__device__ __forceinline__ void bsync(int id) {
    asm volatile("bar.sync %0, 512;" :: "r"(id) : "memory");
}
__device__ __forceinline__ void barrive(int id) {
    asm volatile("bar.arrive %0, 512;" :: "r"(id) : "memory");
}
__device__ __forceinline__ void spin_ge(const int* p, int tgt) {
    int v;
    do {
        asm volatile("ld.acquire.gpu.global.b32 %0, [%1];" : "=r"(v) : "l"(p) : "memory");
    } while (v < tgt);
}
__device__ __forceinline__ void st_rel(int* p, int v) {
    asm volatile("st.release.gpu.global.b32 [%0], %1;" :: "l"(p), "r"(v) : "memory");
}

__global__ void __launch_bounds__(256) convert_weights_kernel(
    const float* __restrict__ W1, const float* __restrict__ Whh,
    const float* __restrict__ Wih, const float* __restrict__ fcW)
{
    int i = blockIdx.x * 256 + threadIdx.x;
    if (i < D_ * E_) {
        int d = i >> 8, c = i & 255;
        g_whc[i] = __floats2half2_rn(W1[d * E_ + c], W1[(D_ + d) * E_ + c]);
    }
    if (i < D_ * 4 * D_)    g_whh[i] = __float2half_rn(Whh[i]);
    if (i < O_ * 4 * D_)    g_wih[i] = __float2half_rn(Wih[i]);
    if (i < O_ * (E_ + O_)) {
        int c = i / 320, k = i % 320;
        g_fcwT[i] = __float2half_rn(fcW[k * 64 + c]);
    }
    if (i < NPAIR * 2 * 3 * 32) ((int*)g_flag)[i] = 0;
}

__global__ void __launch_bounds__(NT, 1) attn_decoder_kernel(
    const float* __restrict__ x, const float* __restrict__ yh,
    const float* __restrict__ h0, const float* __restrict__ c0,
    const float* __restrict__ W1, const float* __restrict__ b1,
    const float* __restrict__ w2, const float* __restrict__ b2,
    const float* __restrict__ bih, const float* __restrict__ bhh,
    const float* __restrict__ fcb)
{
    extern __shared__ char smraw[];
    __half* ep_sm = (__half*)(smraw + OFF_EP);
    __half* x16   = (__half*)(smraw + OFF_X16);
    float*  gsm   = (float*)(smraw + OFF_GS);
    float*  partB = (float*)(smraw + OFF_PB);
    float*  partA = (float*)(smraw + OFF_PA);
    float*  hsm   = (float*)(smraw + OFF_H);
    float*  csm   = (float*)(smraw + OFF_C);
    float*  hcsm  = (float*)(smraw + OFF_HC);
    float*  hcp   = (float*)(smraw + OFF_HCP);
    float*  ctxs  = (float*)(smraw + OFF_CTX);
    float*  gb    = (float*)(smraw + OFF_GB);
    float*  sc    = (float*)(smraw + OFF_SC);
    float*  ysm   = (float*)(smraw + OFF_Y);
    float*  ytlsm = (float*)(smraw + OFF_YT);
    float*  w2s   = (float*)(smraw + OFF_W2);
    float*  fcbs  = (float*)(smraw + OFF_FCB);

    const int pair = blockIdx.x >> 1;
    const int hf   = blockIdx.x & 1;
    const int myb  = 2 * pair + hf;
    const int t    = threadIdx.x;
    const int lane = t & 31, w = t >> 5;

    // ---- prologue (all 512) ----
    const float* xb = x + (size_t)myb * S_ * E_;
    for (int i = t; i < S_ * E_; i += NT) x16[i] = __float2half_rn(xb[i]);
    {
        int bt = t >> 8, d = t & 255;
        hsm[t] = h0[(2 * pair + bt) * D_ + d];
        csm[t] = c0[(2 * pair + bt) * D_ + d];
    }
    float rb1 = 0.f;
    if (t < 256) {
        w2s[t] = w2[t];
        rb1 = b1[t];
        float4 a  = ((const float4*)bih)[t];
        float4 c4 = ((const float4*)bhh)[t];
        ((float4*)gb)[t] = make_float4(a.x + c4.x, a.y + c4.y, a.z + c4.z, a.w + c4.w);
        if (t < O_) fcbs[t] = fcb[t];
    }
    const float b2c = b2[0];
    __syncthreads();

    // ---- enc_proj (own batch, fp32 weights, fp16 result in SMEM) ----
    {
        const float4* We4 = (const float4*)(W1 + 2 * D_ * E_);
        const int r = t >> 6, j = t & 63;
        for (int s0 = 16 * r; s0 < 16 * r + 16; s0 += 8) {
            float4 acc[8];
            #pragma unroll
            for (int q = 0; q < 8; q++) acc[q] = make_float4(0.f, 0.f, 0.f, 0.f);
            for (int e = 0; e < E_; e++) {
                float4 wv = We4[e * 64 + j];
                #pragma unroll
                for (int q = 0; q < 8; q++) {
                    float xv = __half2float(x16[(s0 + q) * E_ + e]);
                    acc[q].x = fmaf(xv, wv.x, acc[q].x);
                    acc[q].y = fmaf(xv, wv.y, acc[q].y);
                    acc[q].z = fmaf(xv, wv.z, acc[q].z);
                    acc[q].w = fmaf(xv, wv.w, acc[q].w);
                }
            }
            #pragma unroll
            for (int q = 0; q < 8; q++) {
                __half2* rowp = (__half2*)(ep_sm + (size_t)(s0 + q) * E_);
                rowp[2 * j]     = __floats2half2_rn(acc[q].x, acc[q].y);
                rowp[2 * j + 1] = __floats2half2_rn(acc[q].z, acc[q].w);
            }
        }
    }
    __syncthreads();

    const uint4* whc4 = (const uint4*)g_whc;   // row d: 64 uint4 (4 half2-cols each)
    const uint4* whh4 = (const uint4*)g_whh;   // row k: 128 uint4 (8 cols each)
    const uint4* wih4 = (const uint4*)g_wih;
    const __half2* x16h2 = (const __half2*)x16;

    if (t < 256) {
        // ==================== GROUP A: attention chain (own batch) ====================
        float w2r[8];
        *(float4*)&w2r[0] = *(float4*)(w2s + 8 * lane);
        *(float4*)&w2r[4] = *(float4*)(w2s + 8 * lane + 4);

        barrive(5);   // h0/c0 staged
        for (int step = 0; step < S_; step++) {
            bsync(3);   // local hc piece + X1 export done by B
            float yv = 0.f;
            if (t < O_) yv = yh[((size_t)myb * S_ + step) * O_ + t];   // prefetch
            spin_ge(&g_flag[pair][1 - hf][0][0], step + 1);
            {
                float hv = ((t >> 7) == hf) ? hcp[t & 127]
                                            : __ldcg(&g_x1[pair][1 - hf][t & 127]);
                hcsm[t] = hv + rb1;
                if (t < O_) ysm[t] = yv;
            }
            barA();

            // scores: warp w -> s = 16w..16w+15
            {
                float hcr[8];
                *(float4*)&hcr[0] = *(float4*)(hcsm + 8 * lane);
                *(float4*)&hcr[4] = *(float4*)(hcsm + 8 * lane + 4);
                #pragma unroll 2
                for (int si = 0; si < 16; si++) {
                    int s = 16 * w + si;
                    uint4 u = ((const uint4*)ep_sm)[(s << 5) + lane];
                    float sum = 0.f;
                    #pragma unroll
                    for (int k = 0; k < 4; k++) {
                        float2 p = __half22float2(((const __half2*)&u)[k]);
                        sum = fmaf(tanh_a(p.x + hcr[2 * k]),     w2r[2 * k],     sum);
                        sum = fmaf(tanh_a(p.y + hcr[2 * k + 1]), w2r[2 * k + 1], sum);
                    }
                    #pragma unroll
                    for (int off = 16; off; off >>= 1)
                        sum += __shfl_xor_sync(0xffffffffu, sum, off);
                    if (lane == 0) sc[s] = sum + b2c;
                }
            }
            barA();

            // softmax by warp 0
            if (w == 0) {
                float v0 = sc[lane], v1 = sc[32 + lane], v2 = sc[64 + lane], v3 = sc[96 + lane];
                float m = fmaxf(fmaxf(v0, v1), fmaxf(v2, v3));
                #pragma unroll
                for (int off = 16; off; off >>= 1)
                    m = fmaxf(m, __shfl_xor_sync(0xffffffffu, m, off));
                float e0 = __expf(v0 - m), e1 = __expf(v1 - m);
                float e2 = __expf(v2 - m), e3 = __expf(v3 - m);
                float s2 = e0 + e1 + e2 + e3;
                #pragma unroll
                for (int off = 16; off; off >>= 1)
                    s2 += __shfl_xor_sync(0xffffffffu, s2, off);
                float inv = __fdividef(1.f, s2);
                sc[lane]      = e0 * inv;
                sc[32 + lane] = e1 * inv;
                sc[64 + lane] = e2 * inv;
                sc[96 + lane] = e3 * inv;
            }
            barA();

            // context partials
            {
                const int e2 = t & 127, sh = t >> 7;
                const int s0 = 64 * sh;
                float2 acc2 = make_float2(0.f, 0.f);
                #pragma unroll 8
                for (int s = s0; s < s0 + 64; s++) {
                    float2 xv = __half22float2(x16h2[s * 128 + e2]);
                    float  al = sc[s];
                    acc2.x = fmaf(al, xv.x, acc2.x);
                    acc2.y = fmaf(al, xv.y, acc2.y);
                }
                ((float2*)partA)[sh * 128 + e2] = acc2;
            }
            barA();
            if (t < 128) {
                float2 a2 = ((float2*)partA)[t];
                float2 b2v = ((float2*)partA)[128 + t];
                ((float2*)ctxs)[t] = make_float2(a2.x + b2v.x, a2.y + b2v.y);
            }
            barA();

            // y_tilde partials
            {
                const int rA = t >> 6, j = t & 63;
                const uint4* fw4 = (const uint4*)(g_fcwT + j * 320);
                float acc = 0.f;
                #pragma unroll 2
                for (int u = 0; u < 10; u++) {
                    uint4 v = fw4[10 * rA + u];
                    int kb = 80 * rA + 8 * u;
                    #pragma unroll
                    for (int q = 0; q < 4; q++) {
                        float2 p = __half22float2(((const __half2*)&v)[q]);
                        int k = kb + 2 * q;
                        float a0 = (k     < E_) ? ctxs[k]     : ysm[k - E_];
                        float a1 = (k + 1 < E_) ? ctxs[k + 1] : ysm[k + 1 - E_];
                        acc = fmaf(a0, p.x, fmaf(a1, p.y, acc));
                    }
                }
                partA[512 + t] = acc;
            }
            barA();
            if (t < O_) {
                float v = fcbs[t] + partA[512 + t] + partA[576 + t]
                                  + partA[640 + t] + partA[704 + t];
                ytlsm[hf * 64 + t] = v;
                g_x2[pair][hf][t] = v;
            }
            __threadfence();
            barA();
            if (t == 0) st_rel(&g_flag[pair][hf][1][0], step + 1);
            barrive(6);

            bsync(4);     // gate partials ready (own column set, both batches)
            {
                const int bb = t >> 7, dl = t & 127;
                const int d = 128 * hf + dl;
                const float* g = gsm + bb * 2048;
                float gq[4];
                #pragma unroll
                for (int q = 0; q < 4; q++) {
                    gq[q] = g[q * 128 + dl] + g[512 + q * 128 + dl]
                          + g[1024 + q * 128 + dl] + g[1536 + q * 128 + dl]
                          + gb[q * 256 + d];
                }
                float cv = csm[bb * 256 + d];
                float cn = fmaf(sigm_f(gq[1]), cv, sigm_f(gq[0]) * tanh_f(gq[2]));
                float hn = sigm_f(gq[3]) * tanh_f(cn);
                hsm[bb * 256 + d] = hn;
                csm[bb * 256 + d] = cn;
                g_x3[pair][hf][bb * 256 + dl]       = hn;
                g_x3[pair][hf][bb * 256 + 128 + dl] = cn;
            }
            __threadfence();
            barA();
            if (t == 0) st_rel(&g_flag[pair][hf][2][0], step + 1);
            barrive(5);
        }

        // epilogue: assemble full h for own batch
        spin_ge(&g_flag[pair][1 - hf][2][0], S_);
        {
            float hval = ((t >> 7) == hf) ? hsm[hf * 256 + t]
                                          : __ldcg(&g_x3[pair][1 - hf][hf * 256 + (t & 127)]);
            g_hctx[myb * 512 + t]       = hval;
            g_hctx[myb * 512 + 256 + t] = ctxs[t];
        }
    } else {
        // ==================== GROUP B: half-column weight streamer ====================
        const int tb   = t - 256;
        const int kq8  = tb >> 5, cq = tb & 31;     // whc: 8 k-splits x 32 uint4-cols
        const int kq4  = tb >> 6, cq2 = tb & 63;    // whh/wih: 4 k-splits x 64 uint4-cols
        const int qg   = cq2 >> 4, qoff = cq2 & 15;
        const int colu = qg * 32 + hf * 16 + qoff;  // uint4 col within 128-wide row

        for (int step = 0; step < S_; step++) {
            bsync(5);   // own halves of h,c staged by A
            if (step > 0) {
                spin_ge(&g_flag[pair][1 - hf][2][0], step);
                const int i0 = tb * 2;
                #pragma unroll
                for (int u = 0; u < 2; u++) {
                    int i = i0 + u;
                    int bbv = i >> 8, rem = i & 255;
                    float v = __ldcg(&g_x3[pair][1 - hf][i]);
                    int d = 128 * (1 - hf) + (rem & 127);
                    if (rem < 128) hsm[bbv * 256 + d] = v;
                    else           csm[bbv * 256 + d] = v;
                }
            }
            barB();

            // ---- whc: cols [128hf..+128), k rows [32kq8..+32), both batches ----
            {
                float a0[4], a1[4];
                #pragma unroll
                for (int i = 0; i < 4; i++) { a0[i] = 0.f; a1[i] = 0.f; }
                const int d0 = 32 * kq8;
                #pragma unroll
                for (int kk = 0; kk < 32; kk += 8) {
                    uint4 v[8];
                    #pragma unroll
                    for (int q = 0; q < 8; q++)
                        v[q] = whc4[(d0 + kk + q) * 64 + 32 * hf + cq];
                    #pragma unroll
                    for (int q = 0; q < 8; q++) {
                        int d = d0 + kk + q;
                        float h0v = hsm[d],        c0v = csm[d];
                        float h1v = hsm[256 + d],  c1v = csm[256 + d];
                        #pragma unroll
                        for (int k = 0; k < 4; k++) {
                            float2 p = __half22float2(((const __half2*)&v[q])[k]);
                            a0[k] = fmaf(h0v, p.x, fmaf(c0v, p.y, a0[k]));
                            a1[k] = fmaf(h1v, p.x, fmaf(c1v, p.y, a1[k]));
                        }
                    }
                }
                #pragma unroll
                for (int k = 0; k < 4; k++) {
                    partB[kq8 * 128 + 4 * cq + k]        = a0[k];
                    partB[1024 + kq8 * 128 + 4 * cq + k] = a1[k];
                }
            }
            barB();
            // reduce + export hc pieces
            {
                const int bbv = tb >> 7, cl = tb & 127;
                const float* pp = partB + bbv * 1024;
                float v = pp[cl] + pp[128 + cl] + pp[256 + cl] + pp[384 + cl]
                        + pp[512 + cl] + pp[640 + cl] + pp[768 + cl] + pp[896 + cl];
                if (bbv == hf) hcp[cl] = v;
                else           g_x1[pair][hf][cl] = v;
            }
            __threadfence();
            barB();
            if (tb == 0) st_rel(&g_flag[pair][hf][0][0], step + 1);
            barrive(3);

            // ---- whh: own gate-column set, k rows [64kq4..+64), both batches ----
            float a0[8], a1[8];
            #pragma unroll
            for (int i = 0; i < 8; i++) { a0[i] = 0.f; a1[i] = 0.f; }
            {
                const int base = 64 * kq4;
                #pragma unroll 2
                for (int k0 = 0; k0 < 64; k0 += 8) {
                    uint4 v[8];
                    #pragma unroll
                    for (int q = 0; q < 8; q++)
                        v[q] = whh4[(base + k0 + q) * 128 + colu];
                    #pragma unroll
                    for (int q = 0; q < 8; q++) {
                        float h0v = hsm[base + k0 + q];
                        float h1v = hsm[256 + base + k0 + q];
                        #pragma unroll
                        for (int k = 0; k < 4; k++) {
                            float2 p = __half22float2(((const __half2*)&v[q])[k]);
                            a0[2 * k]     = fmaf(h0v, p.x, a0[2 * k]);
                            a0[2 * k + 1] = fmaf(h0v, p.y, a0[2 * k + 1]);
                            a1[2 * k]     = fmaf(h1v, p.x, a1[2 * k]);
                            a1[2 * k + 1] = fmaf(h1v, p.y, a1[2 * k + 1]);
                        }
                    }
                }
            }

            bsync(6);   // own ytl ready
            spin_ge(&g_flag[pair][1 - hf][1][0], step + 1);
            if (tb < 64) ytlsm[(1 - hf) * 64 + tb] = __ldcg(&g_x2[pair][1 - hf][tb]);
            barB();

            // ---- wih: accumulate into same registers ----
            {
                const int base = 16 * kq4;
                #pragma unroll
                for (int k0 = 0; k0 < 16; k0 += 8) {
                    uint4 v[8];
                    #pragma unroll
                    for (int q = 0; q < 8; q++)
                        v[q] = wih4[(base + k0 + q) * 128 + colu];
                    #pragma unroll
                    for (int q = 0; q < 8; q++) {
                        float y0v = ytlsm[base + k0 + q];
                        float y1v = ytlsm[64 + base + k0 + q];
                        #pragma unroll
                        for (int k = 0; k < 4; k++) {
                            float2 p = __half22float2(((const __half2*)&v[q])[k]);
                            a0[2 * k]     = fmaf(y0v, p.x, a0[2 * k]);
                            a0[2 * k + 1] = fmaf(y0v, p.y, a0[2 * k + 1]);
                            a1[2 * k]     = fmaf(y1v, p.x, a1[2 * k]);
                            a1[2 * k + 1] = fmaf(y1v, p.y, a1[2 * k + 1]);
                        }
                    }
                }
            }
            {
                float* d0p = gsm + kq4 * 512 + cq2 * 8;
                float* d1p = gsm + 2048 + kq4 * 512 + cq2 * 8;
                ((float4*)d0p)[0] = make_float4(a0[0], a0[1], a0[2], a0[3]);
                ((float4*)d0p)[1] = make_float4(a0[4], a0[5], a0[6], a0[7]);
                ((float4*)d1p)[0] = make_float4(a1[0], a1[1], a1[2], a1[3]);
                ((float4*)d1p)[1] = make_float4(a1[4], a1[5], a1[6], a1[7]);
            }
            barrive(4);
        }
    }
}

// out[128, 8192] = g_hctx[128,512] @ fc_out_W[512,8192] + b
__global__ void __launch_bounds__(256, 1) fcout_kernel(
    const float* __restrict__ W, const float* __restrict__ bias,
    float* __restrict__ out)
{
    __shared__ float As[32][128];
    __shared__ float Ws[32][64];
    const int n0 = blockIdx.x * 64;
    const int t  = threadIdx.x;
    const int tx = t & 7, ty = t >> 3;

    float bv[8];
    #pragma unroll
    for (int jj = 0; jj < 8; jj++) bv[jj] = bias[n0 + 8 * tx + jj];

    float acc[4][8];
    #pragma unroll
    for (int i = 0; i < 4; i++)
        #pragma unroll
        for (int jj = 0; jj < 8; jj++) acc[i][jj] = 0.f;

    for (int k0 = 0; k0 < 512; k0 += 32) {
        {
            int q    = t & 7;
            int row0 = t >> 3;
            #pragma unroll
            for (int i = 0; i < 4; i++) {
                int rr = row0 + 32 * i;
                float4 v = *(const float4*)(g_hctx + rr * 512 + k0 + 4 * q);
                As[4 * q + 0][rr] = v.x;
                As[4 * q + 1][rr] = v.y;
                As[4 * q + 2][rr] = v.z;
                As[4 * q + 3][rr] = v.w;
            }
            int nq  = t & 15;
            int kk0 = t >> 4;
            #pragma unroll
            for (int i = 0; i < 2; i++) {
                int kk = kk0 + 16 * i;
                float4 v = *(const float4*)(W + (size_t)(k0 + kk) * 8192 + n0 + 4 * nq);
                *(float4*)(&Ws[kk][4 * nq]) = v;
            }
        }
        __syncthreads();
        #pragma unroll 8
        for (int kk = 0; kk < 32; kk++) {
            float a[4], wv[8];
            #pragma unroll
            for (int i = 0; i < 4; i++) a[i] = As[kk][4 * ty + i];
            #pragma unroll
            for (int jj = 0; jj < 8; jj++) wv[jj] = Ws[kk][8 * tx + jj];
            #pragma unroll
            for (int i = 0; i < 4; i++)
                #pragma unroll
                for (int jj = 0; jj < 8; jj++)
                    acc[i][jj] = fmaf(a[i], wv[jj], acc[i][jj]);
        }
        __syncthreads();
    }
    #pragma unroll
    for (int i = 0; i < 4; i++) {
        int bb = 4 * ty + i;
        #pragma unroll
        for (int jj = 0; jj < 8; jj++)
            out[(size_t)bb * 8192 + n0 + 8 * tx + jj] = acc[i][jj] + bv[jj];
    }
}

extern "C" void kernel_launch(void* const* d_in, const int* in_sizes, int n_in,
                              void* d_out, int out_size)
{
    const float* x   = (const float*)d_in[0];
    const float* yh  = (const float*)d_in[1];
    const float* h0  = (const float*)d_in[2];
    const float* c0  = (const float*)d_in[3];
    const float* W1  = (const float*)d_in[4];
    const float* b1  = (const float*)d_in[5];
    const float* w2  = (const float*)d_in[6];
    const float* b2  = (const float*)d_in[7];
    const float* Wih = (const float*)d_in[8];
    const float* Whh = (const float*)d_in[9];
    const float* bih = (const float*)d_in[10];
    const float* bhh = (const float*)d_in[11];
    const float* fcW = (const float*)d_in[12];
    const float* fcb = (const float*)d_in[13];
    const float* foW = (const float*)d_in[14];
    const float* fob = (const float*)d_in[15];

    convert_weights_kernel<<<(D_ * 4 * D_ + 255) / 256, 256>>>(W1, Whh, Wih, fcW);

    cudaFuncSetAttribute(attn_decoder_kernel,
                         cudaFuncAttributeMaxDynamicSharedMemorySize, SMEM_BYTES);
    attn_decoder_kernel<<<B_, NT, SMEM_BYTES>>>(x, yh, h0, c0, W1, b1, w2, b2,
                                                bih, bhh, fcb);
    fcout_kernel<<<128, 256>>>(foW, fob, (float*)d_out);
}

// round 9
// speedup vs baseline: 1.4273x; 1.1695x over previous
#include <cuda_runtime.h>
#include <cuda_fp16.h>
#include <math.h>

namespace {
constexpr int B_ = 128, S_ = 128, E_ = 256, D_ = 256, O_ = 64;
constexpr int NT = 512;

// dynamic smem layout (bytes)
constexpr int OFF_X16 = 0;        // half [128][256] own x        65536
constexpr int OFF_XF  = 65536;    // float[128][64] X@fcW[:256]   32768
constexpr int OFF_YF  = 98304;    // float[128][64] y@fcW[256:]+b 32768
constexpr int OFF_GS  = 131072;   // float[6][1024] gate partials 24576
constexpr int OFF_PART= 155648;   // float[8][256]  whc partials   8192
constexpr int OFF_H   = 163840;   // float[256]
constexpr int OFF_C   = 164864;
constexpr int OFF_HC  = 165888;
constexpr int OFF_GB  = 166912;   // float[1024]
constexpr int OFF_SC  = 171008;   // float[128]
constexpr int OFF_YT  = 171520;   // float[64]
constexpr int OFF_W2  = 171776;   // float[256]
constexpr int OFF_PA  = 172800;   // float[256] ytl partials
constexpr int SMEM_BYTES = 173824;
}

// fp16 weight copies + enc_proj (built once per launch)
__device__ __half2 g_whc[D_ * E_];        // (Wh, Wc) interleaved
__device__ __half  g_whh[D_ * 4 * D_];    // [256][1024]
__device__ __half  g_wih[O_ * 4 * D_];    // [64][1024]
__device__ __half  g_ep16[B_ * S_ * E_];  // enc_proj fp16
__device__ float   g_hctx[B_ * (D_ + E_)];

__device__ __forceinline__ float sigm_f(float x) {
    float e = __expf(-x);
    return __fdividef(1.f, 1.f + e);
}
__device__ __forceinline__ float tanh_f(float x) {
    float e = __expf(2.f * x);
    return 1.f - __fdividef(2.f, e + 1.f);
}
__device__ __forceinline__ float tanh_a(float x) {
    float y;
    asm("tanh.approx.f32 %0, %1;" : "=f"(y) : "f"(x));
    return y;
}
__device__ __forceinline__ void barA() { asm volatile("bar.sync 1, 256;" ::: "memory"); }
__device__ __forceinline__ void bsync(int id) {
    asm volatile("bar.sync %0, 512;" :: "r"(id) : "memory");
}
__device__ __forceinline__ void barrive(int id) {
    asm volatile("bar.arrive %0, 512;" :: "r"(id) : "memory");
}

__global__ void __launch_bounds__(256) convert_weights_kernel(
    const float* __restrict__ W1, const float* __restrict__ Whh,
    const float* __restrict__ Wih)
{
    int i = blockIdx.x * 256 + threadIdx.x;
    if (i < D_ * E_) {
        int d = i >> 8, c = i & 255;
        g_whc[i] = __floats2half2_rn(W1[d * E_ + c], W1[(D_ + d) * E_ + c]);
    }
    if (i < D_ * 4 * D_) g_whh[i] = __float2half_rn(Whh[i]);
    if (i < O_ * 4 * D_) g_wih[i] = __float2half_rn(Wih[i]);
}

// enc_proj = x[b] @ We -> g_ep16 (one CTA per batch)
__global__ void __launch_bounds__(512) encproj_kernel(
    const float* __restrict__ x, const float* __restrict__ W1)
{
    extern __shared__ char sm[];
    __half* xs = (__half*)sm;   // [128][256]
    const int b = blockIdx.x, t = threadIdx.x;
    const int r = t >> 6, j = t & 63;

    const float* xb = x + (size_t)b * S_ * E_;
    for (int i = t; i < S_ * E_; i += 512) xs[i] = __float2half_rn(xb[i]);
    __syncthreads();

    const float4* We4 = (const float4*)(W1 + 2 * D_ * E_);
    __half* epb = g_ep16 + (size_t)b * S_ * E_;
    for (int s0 = 16 * r; s0 < 16 * r + 16; s0 += 8) {
        float4 acc[8];
        #pragma unroll
        for (int q = 0; q < 8; q++) acc[q] = make_float4(0.f, 0.f, 0.f, 0.f);
        for (int e = 0; e < E_; e++) {
            float4 wv = We4[e * 64 + j];
            #pragma unroll
            for (int q = 0; q < 8; q++) {
                float xv = __half2float(xs[(s0 + q) * E_ + e]);
                acc[q].x = fmaf(xv, wv.x, acc[q].x);
                acc[q].y = fmaf(xv, wv.y, acc[q].y);
                acc[q].z = fmaf(xv, wv.z, acc[q].z);
                acc[q].w = fmaf(xv, wv.w, acc[q].w);
            }
        }
        #pragma unroll
        for (int q = 0; q < 8; q++) {
            __half2* rowp = (__half2*)(epb + (size_t)(s0 + q) * E_);
            rowp[2 * j]     = __floats2half2_rn(acc[q].x, acc[q].y);
            rowp[2 * j + 1] = __floats2half2_rn(acc[q].z, acc[q].w);
        }
    }
}

__global__ void __launch_bounds__(NT, 1) attn_decoder_kernel(
    const float* __restrict__ x, const float* __restrict__ yh,
    const float* __restrict__ h0, const float* __restrict__ c0,
    const float* __restrict__ b1, const float* __restrict__ w2,
    const float* __restrict__ b2, const float* __restrict__ bih,
    const float* __restrict__ bhh, const float* __restrict__ fcW,
    const float* __restrict__ fcb)
{
    extern __shared__ char smraw[];
    __half* x16  = (__half*)(smraw + OFF_X16);
    float*  XF   = (float*)(smraw + OFF_XF);
    float*  YF   = (float*)(smraw + OFF_YF);
    float*  gsm  = (float*)(smraw + OFF_GS);
    float*  part = (float*)(smraw + OFF_PART);
    float*  hsm  = (float*)(smraw + OFF_H);
    float*  csm  = (float*)(smraw + OFF_C);
    float*  hcsm = (float*)(smraw + OFF_HC);
    float*  gb   = (float*)(smraw + OFF_GB);
    float*  sc   = (float*)(smraw + OFF_SC);
    float*  ytl  = (float*)(smraw + OFF_YT);
    float*  w2s  = (float*)(smraw + OFF_W2);
    float*  partA= (float*)(smraw + OFF_PA);

    const int b    = blockIdx.x;
    const int t    = threadIdx.x;
    const int lane = t & 31, w = t >> 5;
    const int r    = t >> 6, j = t & 63;

    // ---- prologue ----
    const float* xb = x + (size_t)b * S_ * E_;
    for (int i = t; i < S_ * E_; i += NT) x16[i] = __float2half_rn(xb[i]);
    float rb1 = 0.f;
    if (t < 256) {
        w2s[t] = w2[t];
        hsm[t] = h0[b * D_ + t];
        csm[t] = c0[b * D_ + t];
        rb1 = b1[t];
        float4 a  = ((const float4*)bih)[t];
        float4 c4 = ((const float4*)bhh)[t];
        ((float4*)gb)[t] = make_float4(a.x + c4.x, a.y + c4.y, a.z + c4.z, a.w + c4.w);
    }
    const float b2c = b2[0];
    __syncthreads();

    // ---- XF[s][j] = sum_e x[s][e] * fcW[e][j]  (thread: sB rows 16.., col j) ----
    {
        const int sB = t >> 6;
        float acc[16];
        #pragma unroll
        for (int si = 0; si < 16; si++) acc[si] = 0.f;
        for (int e = 0; e < E_; e++) {
            float wv = fcW[e * 64 + j];
            #pragma unroll
            for (int si = 0; si < 16; si++)
                acc[si] = fmaf(__half2float(x16[(16 * sB + si) * E_ + e]), wv, acc[si]);
        }
        #pragma unroll
        for (int si = 0; si < 16; si++) XF[(16 * sB + si) * 64 + j] = acc[si];
    }

    // ---- YF[t][j] = fcb[j] + sum_o yh[b][t][o] * fcW[256+o][j] ----
    {
        const int tB = t >> 6;
        float acc[16];
        #pragma unroll
        for (int si = 0; si < 16; si++) acc[si] = 0.f;
        const float* yhb = yh + (size_t)b * S_ * O_;
        for (int o = 0; o < O_; o++) {
            float wv = fcW[(E_ + o) * 64 + j];
            #pragma unroll
            for (int si = 0; si < 16; si++)
                acc[si] = fmaf(yhb[(16 * tB + si) * O_ + o], wv, acc[si]);
        }
        float fb = fcb[j];
        #pragma unroll
        for (int si = 0; si < 16; si++) YF[(16 * tB + si) * 64 + j] = acc[si] + fb;
    }
    __syncthreads();

    const uint4* whc4 = (const uint4*)g_whc;   // row d: 64 uint4 (4 half2 cols)
    const uint4* whh4 = (const uint4*)g_whh;   // row k: 128 uint4 (8 cols)
    const uint4* wih4 = (const uint4*)g_wih;
    const __half* epb = g_ep16 + (size_t)b * S_ * E_;

    for (int step = 0; step < S_; step++) {
        // ===== whc partials: all 512 threads. rows 32r..+32, cols 4j..+4 =====
        {
            float4 acc = make_float4(0.f, 0.f, 0.f, 0.f);
            const int d0 = 32 * r;
            #pragma unroll
            for (int kk = 0; kk < 32; kk += 8) {
                uint4 v[8];
                #pragma unroll
                for (int q = 0; q < 8; q++) v[q] = whc4[(d0 + kk + q) * 64 + j];
                #pragma unroll
                for (int q = 0; q < 8; q++) {
                    float hv = hsm[d0 + kk + q], cv = csm[d0 + kk + q];
                    float2 p;
                    p = __half22float2(*(__half2*)&v[q].x);
                    acc.x = fmaf(hv, p.x, fmaf(cv, p.y, acc.x));
                    p = __half22float2(*(__half2*)&v[q].y);
                    acc.y = fmaf(hv, p.x, fmaf(cv, p.y, acc.y));
                    p = __half22float2(*(__half2*)&v[q].z);
                    acc.z = fmaf(hv, p.x, fmaf(cv, p.y, acc.z));
                    p = __half22float2(*(__half2*)&v[q].w);
                    acc.w = fmaf(hv, p.x, fmaf(cv, p.y, acc.w));
                }
            }
            ((float4*)(part + r * 256))[j] = acc;
        }
        __syncthreads();   // B1

        if (t < 256) {
            // ============ GROUP A ============
            {
                float v = rb1;
                #pragma unroll
                for (int rr = 0; rr < 8; rr++) v += part[rr * 256 + t];
                hcsm[t] = v;
            }
            barA();

            // scores: warp w -> s = 16w..16w+15 (ep streamed from L2, prefetched)
            {
                float hcr[8], w2r[8];
                *(float4*)&hcr[0] = *(float4*)(hcsm + 8 * lane);
                *(float4*)&hcr[4] = *(float4*)(hcsm + 8 * lane + 4);
                *(float4*)&w2r[0] = *(float4*)(w2s + 8 * lane);
                *(float4*)&w2r[4] = *(float4*)(w2s + 8 * lane + 4);

                const __half* r0 = epb + (16 * w << 8) + 8 * lane;
                uint4 u0 = *(const uint4*)r0;
                for (int si = 0; si < 16; si++) {
                    uint4 n0;
                    if (si < 15) n0 = *(const uint4*)(r0 + 256);
                    float sum = 0.f;
                    #pragma unroll
                    for (int k = 0; k < 4; k++) {
                        float2 p = __half22float2(((const __half2*)&u0)[k]);
                        sum = fmaf(tanh_a(p.x + hcr[2 * k]),     w2r[2 * k],     sum);
                        sum = fmaf(tanh_a(p.y + hcr[2 * k + 1]), w2r[2 * k + 1], sum);
                    }
                    #pragma unroll
                    for (int off = 16; off; off >>= 1)
                        sum += __shfl_xor_sync(0xffffffffu, sum, off);
                    if (lane == 0) sc[16 * w + si] = sum + b2c;
                    u0 = n0; r0 += 256;
                }
            }
            barA();

            // softmax by warp 0
            if (w == 0) {
                float v0 = sc[lane], v1 = sc[32 + lane], v2 = sc[64 + lane], v3 = sc[96 + lane];
                float m = fmaxf(fmaxf(v0, v1), fmaxf(v2, v3));
                #pragma unroll
                for (int off = 16; off; off >>= 1)
                    m = fmaxf(m, __shfl_xor_sync(0xffffffffu, m, off));
                float e0 = __expf(v0 - m), e1 = __expf(v1 - m);
                float e2 = __expf(v2 - m), e3 = __expf(v3 - m);
                float s2 = e0 + e1 + e2 + e3;
                #pragma unroll
                for (int off = 16; off; off >>= 1)
                    s2 += __shfl_xor_sync(0xffffffffu, s2, off);
                float inv = __fdividef(1.f, s2);
                sc[lane]      = e0 * inv;
                sc[32 + lane] = e1 * inv;
                sc[64 + lane] = e2 * inv;
                sc[96 + lane] = e3 * inv;
            }
            barA();

            // ytl = alpha^T XF + YF[step] : partials (sq = t>>6, col j)
            {
                const int sq = t >> 6;
                float acc = 0.f;
                #pragma unroll 8
                for (int s = 32 * sq; s < 32 * sq + 32; s++)
                    acc = fmaf(sc[s], XF[s * 64 + j], acc);
                partA[t] = acc;
            }
            barA();
            if (t < O_) {
                ytl[t] = YF[step * 64 + t] + partA[t] + partA[64 + t]
                       + partA[128 + t] + partA[192 + t];
            }
            barrive(6);   // ytl published for B

            // A's Whh slice: rows 32kq2..+32 (k in [0,64)), cols 8c8..
            {
                const int kq2 = t >> 7, c8 = t & 127;
                float acc[8];
                #pragma unroll
                for (int i = 0; i < 8; i++) acc[i] = 0.f;
                const int base = 32 * kq2;
                #pragma unroll
                for (int k0 = 0; k0 < 32; k0 += 8) {
                    uint4 v[8];
                    #pragma unroll
                    for (int q = 0; q < 8; q++) v[q] = whh4[(base + k0 + q) * 128 + c8];
                    #pragma unroll
                    for (int q = 0; q < 8; q++) {
                        float hv = hsm[base + k0 + q];
                        #pragma unroll
                        for (int k = 0; k < 4; k++) {
                            float2 p = __half22float2(((const __half2*)&v[q])[k]);
                            acc[2 * k]     = fmaf(hv, p.x, acc[2 * k]);
                            acc[2 * k + 1] = fmaf(hv, p.y, acc[2 * k + 1]);
                        }
                    }
                }
                float* dst = gsm + kq2 * 1024 + 8 * c8;
                ((float4*)dst)[0] = make_float4(acc[0], acc[1], acc[2], acc[3]);
                ((float4*)dst)[1] = make_float4(acc[4], acc[5], acc[6], acc[7]);
            }

            bsync(4);     // all gate partials ready
            {
                float gq[4];
                #pragma unroll
                for (int q = 0; q < 4; q++) {
                    float v = gb[q * 256 + t];
                    #pragma unroll
                    for (int p = 0; p < 6; p++) v += gsm[p * 1024 + q * 256 + t];
                    gq[q] = v;
                }
                float cn = fmaf(sigm_f(gq[1]), csm[t], sigm_f(gq[0]) * tanh_f(gq[2]));
                float hn = sigm_f(gq[3]) * tanh_f(cn);
                hsm[t] = hn;
                csm[t] = cn;
            }
        } else {
            // ============ GROUP B: Whh rows 64..255 + Wih ============
            const int tb  = t - 256;
            const int khB = tb >> 7, c8 = tb & 127;

            // Whh rows [64 + 96*khB, +96), cols 8c8..
            {
                float acc[8];
                #pragma unroll
                for (int i = 0; i < 8; i++) acc[i] = 0.f;
                const int base = 64 + 96 * khB;
                #pragma unroll 2
                for (int k0 = 0; k0 < 96; k0 += 8) {
                    uint4 v[8];
                    #pragma unroll
                    for (int q = 0; q < 8; q++) v[q] = whh4[(base + k0 + q) * 128 + c8];
                    #pragma unroll
                    for (int q = 0; q < 8; q++) {
                        float hv = hsm[base + k0 + q];
                        #pragma unroll
                        for (int k = 0; k < 4; k++) {
                            float2 p = __half22float2(((const __half2*)&v[q])[k]);
                            acc[2 * k]     = fmaf(hv, p.x, acc[2 * k]);
                            acc[2 * k + 1] = fmaf(hv, p.y, acc[2 * k + 1]);
                        }
                    }
                }
                float* dst = gsm + (2 + khB) * 1024 + 8 * c8;
                ((float4*)dst)[0] = make_float4(acc[0], acc[1], acc[2], acc[3]);
                ((float4*)dst)[1] = make_float4(acc[4], acc[5], acc[6], acc[7]);
            }

            bsync(6);   // wait ytl

            // Wih rows 32khB..+32, cols 8c8..
            {
                float acc[8];
                #pragma unroll
                for (int i = 0; i < 8; i++) acc[i] = 0.f;
                const int k0b = 32 * khB;
                #pragma unroll
                for (int kk = 0; kk < 32; kk += 8) {
                    uint4 v[8];
                    #pragma unroll
                    for (int q = 0; q < 8; q++) v[q] = wih4[(k0b + kk + q) * 128 + c8];
                    #pragma unroll
                    for (int q = 0; q < 8; q++) {
                        float yv = ytl[k0b + kk + q];
                        #pragma unroll
                        for (int k = 0; k < 4; k++) {
                            float2 p = __half22float2(((const __half2*)&v[q])[k]);
                            acc[2 * k]     = fmaf(yv, p.x, acc[2 * k]);
                            acc[2 * k + 1] = fmaf(yv, p.y, acc[2 * k + 1]);
                        }
                    }
                }
                float* dst = gsm + (4 + khB) * 1024 + 8 * c8;
                ((float4*)dst)[0] = make_float4(acc[0], acc[1], acc[2], acc[3]);
                ((float4*)dst)[1] = make_float4(acc[4], acc[5], acc[6], acc[7]);
            }
            barrive(4);
        }
        __syncthreads();   // B0: h,c updated, visible to all
    }

    // epilogue: context_T = alpha_T^T x (x16 in SMEM), h_T from hsm
    if (t < 256) {
        float acc = 0.f;
        #pragma unroll 4
        for (int s = 0; s < S_; s++)
            acc = fmaf(sc[s], __half2float(x16[s * E_ + t]), acc);
        g_hctx[b * 512 + t]       = hsm[t];
        g_hctx[b * 512 + 256 + t] = acc;
    }
}

// out[128, 8192] = g_hctx[128,512] @ fc_out_W[512,8192] + b
__global__ void __launch_bounds__(256, 1) fcout_kernel(
    const float* __restrict__ W, const float* __restrict__ bias,
    float* __restrict__ out)
{
    __shared__ float As[32][128];
    __shared__ float Ws[32][64];
    const int n0 = blockIdx.x * 64;
    const int t  = threadIdx.x;
    const int tx = t & 7, ty = t >> 3;

    float bv[8];
    #pragma unroll
    for (int jj = 0; jj < 8; jj++) bv[jj] = bias[n0 + 8 * tx + jj];

    float acc[4][8];
    #pragma unroll
    for (int i = 0; i < 4; i++)
        #pragma unroll
        for (int jj = 0; jj < 8; jj++) acc[i][jj] = 0.f;

    for (int k0 = 0; k0 < 512; k0 += 32) {
        {
            int q    = t & 7;
            int row0 = t >> 3;
            #pragma unroll
            for (int i = 0; i < 4; i++) {
                int rr = row0 + 32 * i;
                float4 v = *(const float4*)(g_hctx + rr * 512 + k0 + 4 * q);
                As[4 * q + 0][rr] = v.x;
                As[4 * q + 1][rr] = v.y;
                As[4 * q + 2][rr] = v.z;
                As[4 * q + 3][rr] = v.w;
            }
            int nq  = t & 15;
            int kk0 = t >> 4;
            #pragma unroll
            for (int i = 0; i < 2; i++) {
                int kk = kk0 + 16 * i;
                float4 v = *(const float4*)(W + (size_t)(k0 + kk) * 8192 + n0 + 4 * nq);
                *(float4*)(&Ws[kk][4 * nq]) = v;
            }
        }
        __syncthreads();
        #pragma unroll 8
        for (int kk = 0; kk < 32; kk++) {
            float a[4], wv[8];
            #pragma unroll
            for (int i = 0; i < 4; i++) a[i] = As[kk][4 * ty + i];
            #pragma unroll
            for (int jj = 0; jj < 8; jj++) wv[jj] = Ws[kk][8 * tx + jj];
            #pragma unroll
            for (int i = 0; i < 4; i++)
                #pragma unroll
                for (int jj = 0; jj < 8; jj++)
                    acc[i][jj] = fmaf(a[i], wv[jj], acc[i][jj]);
        }
        __syncthreads();
    }
    #pragma unroll
    for (int i = 0; i < 4; i++) {
        int bb = 4 * ty + i;
        #pragma unroll
        for (int jj = 0; jj < 8; jj++)
            out[(size_t)bb * 8192 + n0 + 8 * tx + jj] = acc[i][jj] + bv[jj];
    }
}

extern "C" void kernel_launch(void* const* d_in, const int* in_sizes, int n_in,
                              void* d_out, int out_size)
{
    const float* x   = (const float*)d_in[0];
    const float* yh  = (const float*)d_in[1];
    const float* h0  = (const float*)d_in[2];
    const float* c0  = (const float*)d_in[3];
    const float* W1  = (const float*)d_in[4];
    const float* b1  = (const float*)d_in[5];
    const float* w2  = (const float*)d_in[6];
    const float* b2  = (const float*)d_in[7];
    const float* Wih = (const float*)d_in[8];
    const float* Whh = (const float*)d_in[9];
    const float* bih = (const float*)d_in[10];
    const float* bhh = (const float*)d_in[11];
    const float* fcW = (const float*)d_in[12];
    const float* fcb = (const float*)d_in[13];
    const float* foW = (const float*)d_in[14];
    const float* fob = (const float*)d_in[15];

    convert_weights_kernel<<<(D_ * 4 * D_ + 255) / 256, 256>>>(W1, Whh, Wih);

    cudaFuncSetAttribute(encproj_kernel,
                         cudaFuncAttributeMaxDynamicSharedMemorySize, S_ * E_ * 2);
    encproj_kernel<<<B_, 512, S_ * E_ * 2>>>(x, W1);

    cudaFuncSetAttribute(attn_decoder_kernel,
                         cudaFuncAttributeMaxDynamicSharedMemorySize, SMEM_BYTES);
    attn_decoder_kernel<<<B_, NT, SMEM_BYTES>>>(x, yh, h0, c0, b1, w2, b2,
                                                bih, bhh, fcW, fcb);
    fcout_kernel<<<128, 256>>>(foW, fob, (float*)d_out);
}

// round 11
// speedup vs baseline: 1.5534x; 1.0884x over previous
#include <cuda_runtime.h>
#include <cuda_fp16.h>
#include <cstdint>
#include <math.h>

namespace {
constexpr int B_ = 128, S_ = 128, E_ = 256, D_ = 256, O_ = 64;
constexpr int NT = 512;

// dynamic smem layout (bytes)
constexpr int OFF_EP   = 0;        // half [128][256] own-batch enc_proj 65536
constexpr int OFF_XF   = 65536;    // f32 [128][64]                     32768
constexpr int OFF_YF   = 98304;    // f32 [128][64] (incl fcb)          32768
constexpr int OFF_SCR  = 131072;   // 64KB overlap: prologue x16 / loop partials
constexpr int OFF_PWHC = OFF_SCR;             // f32[16][2][128] 16384
constexpr int OFF_PWHH = OFF_SCR + 16384;     // f32[4][2][512]  16384
constexpr int OFF_GFIN = OFF_SCR + 32768;     // f32[2][512]      4096
constexpr int OFF_PA   = OFF_SCR + 36864;     // f32[256] ytl partials
// persistent small (outside overlap)
constexpr int OFF_H    = 196608;   // f32[2][256]
constexpr int OFF_C    = 198656;   // f32[2][256]
constexpr int OFF_HC   = 200704;   // f32[256] own-batch hc
constexpr int OFF_SC   = 201728;   // f32[128]
constexpr int OFF_YT   = 202240;   // f32[2][64] ytl both batches
constexpr int OFF_GB   = 202752;   // f32[1024]
constexpr int OFF_W2   = 206848;   // f32[256]
constexpr int OFF_B1   = 207872;   // f32[256]
constexpr int SMEM_BYTES = 208896;
}

// fp16 weights + enc_proj (built once per launch)
__device__ __half2 g_whc[D_ * E_];        // (Wh, Wc) interleaved [d][c]
__device__ __half  g_whh[D_ * 4 * D_];    // [256][1024]
__device__ __half  g_wih[O_ * 4 * D_];    // [64][1024]
__device__ __half  g_ep16[B_ * S_ * E_];
__device__ float   g_hctx[B_ * (D_ + E_)];

__device__ __forceinline__ float sigm_f(float x) {
    float e = __expf(-x);
    return __fdividef(1.f, 1.f + e);
}
__device__ __forceinline__ float tanh_f(float x) {
    float e = __expf(2.f * x);
    return 1.f - __fdividef(2.f, e + 1.f);
}
__device__ __forceinline__ float tanh_a(float x) {
    float y;
    asm("tanh.approx.f32 %0, %1;" : "=f"(y) : "f"(x));
    return y;
}
__device__ __forceinline__ void barA() { asm volatile("bar.sync 1, 256;" ::: "memory"); }
__device__ __forceinline__ void cluster_sync() {
    asm volatile("barrier.cluster.arrive.aligned;" ::: "memory");
    asm volatile("barrier.cluster.wait.aligned;" ::: "memory");
}
__device__ __forceinline__ unsigned int smem_u32(const void* p) {
    unsigned int a;
    asm("{ .reg .u64 t; cvta.to.shared.u64 t, %1; cvt.u32.u64 %0, t; }" : "=r"(a) : "l"(p));
    return a;
}
__device__ __forceinline__ unsigned int mapa_u32(unsigned int a, unsigned int rank) {
    unsigned int r;
    asm("mapa.shared::cluster.u32 %0, %1, %2;" : "=r"(r) : "r"(a), "r"(rank));
    return r;
}
__device__ __forceinline__ void stc_f32(unsigned int a, float v) {
    asm volatile("st.shared::cluster.f32 [%0], %1;" :: "r"(a), "f"(v) : "memory");
}

__global__ void __launch_bounds__(256) convert_weights_kernel(
    const float* __restrict__ W1, const float* __restrict__ Whh,
    const float* __restrict__ Wih)
{
    int i = blockIdx.x * 256 + threadIdx.x;
    if (i < D_ * E_) {
        int d = i >> 8, c = i & 255;
        g_whc[i] = __floats2half2_rn(W1[d * E_ + c], W1[(D_ + d) * E_ + c]);
    }
    if (i < D_ * 4 * D_) g_whh[i] = __float2half_rn(Whh[i]);
    if (i < O_ * 4 * D_) g_wih[i] = __float2half_rn(Wih[i]);
}

// enc_proj = x[b] @ We -> g_ep16 (one CTA per batch)
__global__ void __launch_bounds__(512) encproj_kernel(
    const float* __restrict__ x, const float* __restrict__ W1)
{
    extern __shared__ char sm[];
    __half* xs = (__half*)sm;
    const int b = blockIdx.x, t = threadIdx.x;
    const int r = t >> 6, j = t & 63;

    const float* xb = x + (size_t)b * S_ * E_;
    for (int i = t; i < S_ * E_; i += 512) xs[i] = __float2half_rn(xb[i]);
    __syncthreads();

    const float4* We4 = (const float4*)(W1 + 2 * D_ * E_);
    __half* epb = g_ep16 + (size_t)b * S_ * E_;
    for (int s0 = 16 * r; s0 < 16 * r + 16; s0 += 8) {
        float4 acc[8];
        #pragma unroll
        for (int q = 0; q < 8; q++) acc[q] = make_float4(0.f, 0.f, 0.f, 0.f);
        for (int e = 0; e < E_; e++) {
            float4 wv = We4[e * 64 + j];
            #pragma unroll
            for (int q = 0; q < 8; q++) {
                float xv = __half2float(xs[(s0 + q) * E_ + e]);
                acc[q].x = fmaf(xv, wv.x, acc[q].x);
                acc[q].y = fmaf(xv, wv.y, acc[q].y);
                acc[q].z = fmaf(xv, wv.z, acc[q].z);
                acc[q].w = fmaf(xv, wv.w, acc[q].w);
            }
        }
        #pragma unroll
        for (int q = 0; q < 8; q++) {
            __half2* rowp = (__half2*)(epb + (size_t)(s0 + q) * E_);
            rowp[2 * j]     = __floats2half2_rn(acc[q].x, acc[q].y);
            rowp[2 * j + 1] = __floats2half2_rn(acc[q].z, acc[q].w);
        }
    }
}

__global__ void __launch_bounds__(NT, 1) __cluster_dims__(2, 1, 1)
attn_decoder_kernel(
    const float* __restrict__ x, const float* __restrict__ yh,
    const float* __restrict__ h0, const float* __restrict__ c0,
    const float* __restrict__ b1, const float* __restrict__ w2,
    const float* __restrict__ b2, const float* __restrict__ bih,
    const float* __restrict__ bhh, const float* __restrict__ fcW,
    const float* __restrict__ fcb)
{
    extern __shared__ char smraw[];
    __half* ep_sm = (__half*)(smraw + OFF_EP);
    float*  XF    = (float*)(smraw + OFF_XF);
    float*  YF    = (float*)(smraw + OFF_YF);
    __half* x16   = (__half*)(smraw + OFF_SCR);   // prologue only
    float*  pwhc  = (float*)(smraw + OFF_PWHC);
    float*  pwhh  = (float*)(smraw + OFF_PWHH);
    float*  gfin  = (float*)(smraw + OFF_GFIN);
    float*  partA = (float*)(smraw + OFF_PA);
    float*  hsm   = (float*)(smraw + OFF_H);      // [2][256] both batches
    float*  csm   = (float*)(smraw + OFF_C);
    float*  hcsm  = (float*)(smraw + OFF_HC);     // own batch full hc
    float*  sc    = (float*)(smraw + OFF_SC);
    float*  ytl2  = (float*)(smraw + OFF_YT);     // [2][64]
    float*  gb    = (float*)(smraw + OFF_GB);
    float*  w2s   = (float*)(smraw + OFF_W2);
    float*  b1s   = (float*)(smraw + OFF_B1);

    const int myb  = blockIdx.x;
    const int rho  = blockIdx.x & 1;          // cluster rank
    const int pb   = blockIdx.x & ~1;         // pair base batch
    const int t    = threadIdx.x;
    const int lane = t & 31, w = t >> 5;

    const unsigned int peer_base = mapa_u32(smem_u32(smraw), 1 - rho);

    // ---- prologue ----
    const float* xb = x + (size_t)myb * S_ * E_;
    for (int i = t; i < S_ * E_; i += NT) x16[i] = __float2half_rn(xb[i]);
    {   // load ep16 -> SMEM
        const uint4* eps = (const uint4*)(g_ep16 + (size_t)myb * S_ * E_);
        uint4* epd = (uint4*)ep_sm;
        for (int i = t; i < S_ * E_ / 8; i += NT) epd[i] = eps[i];
    }
    {   // h,c for BOTH batches of the pair
        int bt = t >> 8, d = t & 255;
        hsm[t] = h0[(pb + bt) * D_ + d];
        csm[t] = c0[(pb + bt) * D_ + d];
    }
    if (t < 256) {
        w2s[t] = w2[t];
        b1s[t] = b1[t];
        float4 a  = ((const float4*)bih)[t];
        float4 c4 = ((const float4*)bhh)[t];
        ((float4*)gb)[t] = make_float4(a.x + c4.x, a.y + c4.y, a.z + c4.z, a.w + c4.w);
    }
    const float b2c = b2[0];
    __syncthreads();

    // XF[s][j] = sum_e x[s][e]*fcW[e][j]
    {
        const int sB = t >> 6, j = t & 63;
        float acc[16];
        #pragma unroll
        for (int si = 0; si < 16; si++) acc[si] = 0.f;
        for (int e = 0; e < E_; e++) {
            float wv = fcW[e * 64 + j];
            #pragma unroll
            for (int si = 0; si < 16; si++)
                acc[si] = fmaf(__half2float(x16[(16 * sB + si) * E_ + e]), wv, acc[si]);
        }
        #pragma unroll
        for (int si = 0; si < 16; si++) XF[(16 * sB + si) * 64 + j] = acc[si];
    }
    // YF[t][j] = fcb[j] + sum_o yh[myb][t][o]*fcW[256+o][j]
    {
        const int tB = t >> 6, j = t & 63;
        float acc[16];
        #pragma unroll
        for (int si = 0; si < 16; si++) acc[si] = 0.f;
        const float* yhb = yh + (size_t)myb * S_ * O_;
        for (int o = 0; o < O_; o++) {
            float wv = fcW[(E_ + o) * 64 + j];
            #pragma unroll
            for (int si = 0; si < 16; si++)
                acc[si] = fmaf(yhb[(16 * tB + si) * O_ + o], wv, acc[si]);
        }
        float fb = fcb[j];
        #pragma unroll
        for (int si = 0; si < 16; si++) YF[(16 * tB + si) * 64 + j] = acc[si] + fb;
    }
    __syncthreads();   // x16 region now free -> partials
    cluster_sync();    // both CTAs initialized before any peer writes

    const uint4* whc4 = (const uint4*)g_whc;   // row d: 64 uint4
    const uint4* whh4 = (const uint4*)g_whh;   // row k: 128 uint4
    const unsigned int* wihu = (const unsigned int*)g_wih;   // row k: 512 half2

    for (int step = 0; step < S_; step++) {
        // ===== Phase 1: whc partials, own-half cols, both batches =====
        {
            const int ks = t >> 5, cu = t & 31;
            const int d0 = 16 * ks;
            float a0[4], a1[4];
            #pragma unroll
            for (int i = 0; i < 4; i++) { a0[i] = 0.f; a1[i] = 0.f; }
            #pragma unroll
            for (int kk = 0; kk < 16; kk += 8) {
                uint4 v[8];
                #pragma unroll
                for (int q = 0; q < 8; q++)
                    v[q] = whc4[(d0 + kk + q) * 64 + rho * 32 + cu];
                #pragma unroll
                for (int q = 0; q < 8; q++) {
                    int d = d0 + kk + q;
                    float h0v = hsm[d], c0v = csm[d];
                    float h1v = hsm[256 + d], c1v = csm[256 + d];
                    #pragma unroll
                    for (int k = 0; k < 4; k++) {
                        float2 p = __half22float2(((const __half2*)&v[q])[k]);
                        a0[k] = fmaf(h0v, p.x, fmaf(c0v, p.y, a0[k]));
                        a1[k] = fmaf(h1v, p.x, fmaf(c1v, p.y, a1[k]));
                    }
                }
            }
            ((float4*)(pwhc + (ks * 2 + 0) * 128))[cu] = make_float4(a0[0], a0[1], a0[2], a0[3]);
            ((float4*)(pwhc + (ks * 2 + 1) * 128))[cu] = make_float4(a1[0], a1[1], a1[2], a1[3]);
        }
        __syncthreads();
        if (t < 256) {   // reduce + route hc pieces
            const int bt = t >> 7, cl = t & 127;
            float v = b1s[128 * rho + cl];
            #pragma unroll
            for (int ks = 0; ks < 16; ks++) v += pwhc[(ks * 2 + bt) * 128 + cl];
            if (bt == rho) hcsm[128 * rho + cl] = v;
            else stc_f32(peer_base + OFF_HC + 4 * (128 * rho + cl), v);
        }
        cluster_sync();   // #1 — hc complete in every CTA

        if (t < 256) {
            // ===== Phase 2A: scores -> softmax -> ytl (own batch) =====
            float hcr[8], w2r[8];
            *(float4*)&hcr[0] = *(float4*)(hcsm + 8 * lane);
            *(float4*)&hcr[4] = *(float4*)(hcsm + 8 * lane + 4);
            *(float4*)&w2r[0] = *(float4*)(w2s + 8 * lane);
            *(float4*)&w2r[4] = *(float4*)(w2s + 8 * lane + 4);
            #pragma unroll 2
            for (int si = 0; si < 16; si++) {
                int s = 16 * w + si;
                uint4 u = ((const uint4*)ep_sm)[(s << 5) + lane];
                float sum = 0.f;
                #pragma unroll
                for (int k = 0; k < 4; k++) {
                    float2 p = __half22float2(((const __half2*)&u)[k]);
                    sum = fmaf(tanh_a(p.x + hcr[2 * k]),     w2r[2 * k],     sum);
                    sum = fmaf(tanh_a(p.y + hcr[2 * k + 1]), w2r[2 * k + 1], sum);
                }
                #pragma unroll
                for (int off = 16; off; off >>= 1)
                    sum += __shfl_xor_sync(0xffffffffu, sum, off);
                if (lane == 0) sc[s] = sum + b2c;
            }
            barA();
            if (w == 0) {
                float v0 = sc[lane], v1 = sc[32 + lane], v2 = sc[64 + lane], v3 = sc[96 + lane];
                float m = fmaxf(fmaxf(v0, v1), fmaxf(v2, v3));
                #pragma unroll
                for (int off = 16; off; off >>= 1)
                    m = fmaxf(m, __shfl_xor_sync(0xffffffffu, m, off));
                float e0 = __expf(v0 - m), e1 = __expf(v1 - m);
                float e2 = __expf(v2 - m), e3 = __expf(v3 - m);
                float s2 = e0 + e1 + e2 + e3;
                #pragma unroll
                for (int off = 16; off; off >>= 1)
                    s2 += __shfl_xor_sync(0xffffffffu, s2, off);
                float inv = __fdividef(1.f, s2);
                sc[lane]      = e0 * inv;
                sc[32 + lane] = e1 * inv;
                sc[64 + lane] = e2 * inv;
                sc[96 + lane] = e3 * inv;
            }
            barA();
            {   // ytl = alpha^T XF + YF[step]
                const int sq = t >> 6, j = t & 63;
                float acc = 0.f;
                #pragma unroll 8
                for (int s = 32 * sq; s < 32 * sq + 32; s++)
                    acc = fmaf(sc[s], XF[s * 64 + j], acc);
                partA[t] = acc;
            }
            barA();
            if (t < O_) {
                float v = YF[step * 64 + t] + partA[t] + partA[64 + t]
                        + partA[128 + t] + partA[192 + t];
                ytl2[rho * 64 + t] = v;
                stc_f32(peer_base + OFF_YT + 4 * (rho * 64 + t), v);
            }
        } else {
            // ===== Phase 2B: Whh own-half cols, k=0..255, both batches =====
            const int tb  = t - 256;
            const int khB = tb >> 6, cu2 = tb & 63;
            const int q   = cu2 >> 4, c16 = cu2 & 15;
            const int colu = q * 32 + rho * 16 + c16;
            float a0[8], a1[8];
            #pragma unroll
            for (int i = 0; i < 8; i++) { a0[i] = 0.f; a1[i] = 0.f; }
            const int base = 64 * khB;
            #pragma unroll 2
            for (int k0 = 0; k0 < 64; k0 += 8) {
                uint4 v[8];
                #pragma unroll
                for (int qq = 0; qq < 8; qq++)
                    v[qq] = whh4[(base + k0 + qq) * 128 + colu];
                #pragma unroll
                for (int qq = 0; qq < 8; qq++) {
                    float h0v = hsm[base + k0 + qq];
                    float h1v = hsm[256 + base + k0 + qq];
                    #pragma unroll
                    for (int k = 0; k < 4; k++) {
                        float2 p = __half22float2(((const __half2*)&v[qq])[k]);
                        a0[2 * k]     = fmaf(h0v, p.x, a0[2 * k]);
                        a0[2 * k + 1] = fmaf(h0v, p.y, a0[2 * k + 1]);
                        a1[2 * k]     = fmaf(h1v, p.x, a1[2 * k]);
                        a1[2 * k + 1] = fmaf(h1v, p.y, a1[2 * k + 1]);
                    }
                }
            }
            float* d0p = pwhh + (khB * 2 + 0) * 512 + q * 128 + c16 * 8;
            float* d1p = pwhh + (khB * 2 + 1) * 512 + q * 128 + c16 * 8;
            ((float4*)d0p)[0] = make_float4(a0[0], a0[1], a0[2], a0[3]);
            ((float4*)d0p)[1] = make_float4(a0[4], a0[5], a0[6], a0[7]);
            ((float4*)d1p)[0] = make_float4(a1[0], a1[1], a1[2], a1[3]);
            ((float4*)d1p)[1] = make_float4(a1[4], a1[5], a1[6], a1[7]);
        }
        cluster_sync();   // #2 — ytl both batches + Whh partials ready

        // ===== Phase 3: wih + gate assemble (threads 0..255), both batches =====
        if (t < 256) {
            const int q = t >> 6, p = t & 63;
            const int cidx  = q * 128 + 64 * rho + p;   // half2 col in wih row
            const int hc512 = q * 128 + 2 * p;
            float2 acc0 = make_float2(0.f, 0.f), acc1 = make_float2(0.f, 0.f);
            #pragma unroll 2
            for (int k0 = 0; k0 < 64; k0 += 8) {
                unsigned int u[8];
                #pragma unroll
                for (int qq = 0; qq < 8; qq++) u[qq] = wihu[(k0 + qq) * 512 + cidx];
                #pragma unroll
                for (int qq = 0; qq < 8; qq++) {
                    float y0 = ytl2[k0 + qq], y1 = ytl2[64 + k0 + qq];
                    float2 pw = __half22float2(*(__half2*)&u[qq]);
                    acc0.x = fmaf(y0, pw.x, acc0.x);
                    acc0.y = fmaf(y0, pw.y, acc0.y);
                    acc1.x = fmaf(y1, pw.x, acc1.x);
                    acc1.y = fmaf(y1, pw.y, acc1.y);
                }
            }
            #pragma unroll
            for (int ks = 0; ks < 4; ks++) {
                acc0.x += pwhh[(ks * 2 + 0) * 512 + hc512];
                acc0.y += pwhh[(ks * 2 + 0) * 512 + hc512 + 1];
                acc1.x += pwhh[(ks * 2 + 1) * 512 + hc512];
                acc1.y += pwhh[(ks * 2 + 1) * 512 + hc512 + 1];
            }
            float2 gbv = *(const float2*)(gb + q * 256 + 128 * rho + 2 * p);
            acc0.x += gbv.x; acc0.y += gbv.y;
            acc1.x += gbv.x; acc1.y += gbv.y;
            *(float2*)(gfin + hc512)       = acc0;
            *(float2*)(gfin + 512 + hc512) = acc1;
        }
        __syncthreads();
        if (t < 256) {   // pointwise: own-half d, both batches; export to peer
            const int bt = t >> 7, dl = t & 127;
            const int d = 128 * rho + dl;
            const float* g = gfin + bt * 512;
            float gi = g[dl], gf = g[128 + dl], gg = g[256 + dl], go = g[384 + dl];
            float cv = csm[bt * 256 + d];
            float cn = fmaf(sigm_f(gf), cv, sigm_f(gi) * tanh_f(gg));
            float hn = sigm_f(go) * tanh_f(cn);
            hsm[bt * 256 + d] = hn;
            csm[bt * 256 + d] = cn;
            stc_f32(peer_base + OFF_H + 4 * (bt * 256 + d), hn);
            stc_f32(peer_base + OFF_C + 4 * (bt * 256 + d), cn);
        }
        cluster_sync();   // #3 — full h,c everywhere
    }

    // epilogue: h_T + context_T for own batch (context from global x, final alpha)
    if (t < 256) {
        float acc = 0.f;
        const float* xg = x + (size_t)myb * S_ * E_;
        #pragma unroll 4
        for (int s = 0; s < S_; s++)
            acc = fmaf(sc[s], xg[s * E_ + t], acc);
        g_hctx[myb * 512 + t]       = hsm[rho * 256 + t];
        g_hctx[myb * 512 + 256 + t] = acc;
    }
    cluster_sync();   // no CTA exits while peer may still write our SMEM
}

// out[128, 8192] = g_hctx[128,512] @ fc_out_W[512,8192] + b
__global__ void __launch_bounds__(256, 1) fcout_kernel(
    const float* __restrict__ W, const float* __restrict__ bias,
    float* __restrict__ out)
{
    __shared__ float As[32][128];
    __shared__ float Ws[32][64];
    const int n0 = blockIdx.x * 64;
    const int t  = threadIdx.x;
    const int tx = t & 7, ty = t >> 3;

    float bv[8];
    #pragma unroll
    for (int jj = 0; jj < 8; jj++) bv[jj] = bias[n0 + 8 * tx + jj];

    float acc[4][8];
    #pragma unroll
    for (int i = 0; i < 4; i++)
        #pragma unroll
        for (int jj = 0; jj < 8; jj++) acc[i][jj] = 0.f;

    for (int k0 = 0; k0 < 512; k0 += 32) {
        {
            int q    = t & 7;
            int row0 = t >> 3;
            #pragma unroll
            for (int i = 0; i < 4; i++) {
                int rr = row0 + 32 * i;
                float4 v = *(const float4*)(g_hctx + rr * 512 + k0 + 4 * q);
                As[4 * q + 0][rr] = v.x;
                As[4 * q + 1][rr] = v.y;
                As[4 * q + 2][rr] = v.z;
                As[4 * q + 3][rr] = v.w;
            }
            int nq  = t & 15;
            int kk0 = t >> 4;
            #pragma unroll
            for (int i = 0; i < 2; i++) {
                int kk = kk0 + 16 * i;
                float4 v = *(const float4*)(W + (size_t)(k0 + kk) * 8192 + n0 + 4 * nq);
                *(float4*)(&Ws[kk][4 * nq]) = v;
            }
        }
        __syncthreads();
        #pragma unroll 8
        for (int kk = 0; kk < 32; kk++) {
            float a[4], wv[8];
            #pragma unroll
            for (int i = 0; i < 4; i++) a[i] = As[kk][4 * ty + i];
            #pragma unroll
            for (int jj = 0; jj < 8; jj++) wv[jj] = Ws[kk][8 * tx + jj];
            #pragma unroll
            for (int i = 0; i < 4; i++)
                #pragma unroll
                for (int jj = 0; jj < 8; jj++)
                    acc[i][jj] = fmaf(a[i], wv[jj], acc[i][jj]);
        }
        __syncthreads();
    }
    #pragma unroll
    for (int i = 0; i < 4; i++) {
        int bb = 4 * ty + i;
        #pragma unroll
        for (int jj = 0; jj < 8; jj++)
            out[(size_t)bb * 8192 + n0 + 8 * tx + jj] = acc[i][jj] + bv[jj];
    }
}

extern "C" void kernel_launch(void* const* d_in, const int* in_sizes, int n_in,
                              void* d_out, int out_size)
{
    const float* x   = (const float*)d_in[0];
    const float* yh  = (const float*)d_in[1];
    const float* h0  = (const float*)d_in[2];
    const float* c0  = (const float*)d_in[3];
    const float* W1  = (const float*)d_in[4];
    const float* b1  = (const float*)d_in[5];
    const float* w2  = (const float*)d_in[6];
    const float* b2  = (const float*)d_in[7];
    const float* Wih = (const float*)d_in[8];
    const float* Whh = (const float*)d_in[9];
    const float* bih = (const float*)d_in[10];
    const float* bhh = (const float*)d_in[11];
    const float* fcW = (const float*)d_in[12];
    const float* fcb = (const float*)d_in[13];
    const float* foW = (const float*)d_in[14];
    const float* fob = (const float*)d_in[15];

    convert_weights_kernel<<<(D_ * 4 * D_ + 255) / 256, 256>>>(W1, Whh, Wih);

    cudaFuncSetAttribute(encproj_kernel,
                         cudaFuncAttributeMaxDynamicSharedMemorySize, S_ * E_ * 2);
    encproj_kernel<<<B_, 512, S_ * E_ * 2>>>(x, W1);

    cudaFuncSetAttribute(attn_decoder_kernel,
                         cudaFuncAttributeMaxDynamicSharedMemorySize, SMEM_BYTES);
    attn_decoder_kernel<<<B_, NT, SMEM_BYTES>>>(x, yh, h0, c0, b1, w2, b2,
                                                bih, bhh, fcW, fcb);
    fcout_kernel<<<128, 256>>>(foW, fob, (float*)d_out);
}

// round 12
// speedup vs baseline: 1.5629x; 1.0061x over previous
#include <cuda_runtime.h>
#include <cuda_fp16.h>
#include <cstdint>
#include <math.h>

namespace {
constexpr int B_ = 128, S_ = 128, E_ = 256, D_ = 256, O_ = 64;
constexpr int NT = 512;

// dynamic smem layout (bytes)
constexpr int OFF_EP   = 0;        // half [128][256] own-batch enc_proj 65536
constexpr int OFF_XF   = 65536;    // f32 [128][64]                     32768
constexpr int OFF_YF   = 98304;    // f32 [128][64] (incl fcb)          32768
constexpr int OFF_SCR  = 131072;   // 64KB overlap: prologue x16 / loop partials
constexpr int OFF_PWHC = OFF_SCR;             // f32[16][2][128] 16384
constexpr int OFF_PWHH = OFF_SCR + 16384;     // f32[4][2][512]  16384
constexpr int OFF_GFIN = OFF_SCR + 32768;     // f32[2][512]      4096
constexpr int OFF_PA   = OFF_SCR + 36864;     // f32[256] ytl partials
// persistent small (outside overlap)
constexpr int OFF_H    = 196608;   // f32[2][256]
constexpr int OFF_C    = 198656;   // f32[2][256]
constexpr int OFF_HC   = 200704;   // f32[256] own-batch hc
constexpr int OFF_SC   = 201728;   // f32[128]
constexpr int OFF_YT   = 202240;   // f32[2][64] ytl both batches
constexpr int OFF_GB   = 202752;   // f32[1024]
constexpr int OFF_W2   = 206848;   // f32[256]
constexpr int OFF_B1   = 207872;   // f32[256]
constexpr int SMEM_BYTES = 208896;
}

typedef unsigned long long ull;

// fp16 weights + enc_proj (built once per launch)
__device__ __half2 g_whc[D_ * E_];        // (Wh, Wc) interleaved [d][c]
__device__ __half  g_whh[D_ * 4 * D_];    // [256][1024]
__device__ __half  g_wih[O_ * 4 * D_];    // [64][1024]
__device__ __half  g_ep16[B_ * S_ * E_];
__device__ float   g_hctx[B_ * (D_ + E_)];

__device__ __forceinline__ float sigm_f(float x) {
    float e = __expf(-x);
    return __fdividef(1.f, 1.f + e);
}
__device__ __forceinline__ float tanh_f(float x) {
    float e = __expf(2.f * x);
    return 1.f - __fdividef(2.f, e + 1.f);
}
__device__ __forceinline__ float tanh_a(float x) {
    float y;
    asm("tanh.approx.f32 %0, %1;" : "=f"(y) : "f"(x));
    return y;
}
// packed f32x2 helpers (FFMA2 — PTX-only on sm_103a)
__device__ __forceinline__ ull pack2(float lo, float hi) {
    ull r;
    asm("mov.b64 %0, {%1, %2};" : "=l"(r) : "f"(lo), "f"(hi));
    return r;
}
__device__ __forceinline__ ull fma2(ull a, ull b, ull c) {
    ull d;
    asm("fma.rn.f32x2 %0, %1, %2, %3;" : "=l"(d) : "l"(a), "l"(b), "l"(c));
    return d;
}
__device__ __forceinline__ float2 unpack2(ull v) {
    float2 f;
    asm("mov.b64 {%0, %1}, %2;" : "=f"(f.x), "=f"(f.y) : "l"(v));
    return f;
}
__device__ __forceinline__ ull h2_to_ull(__half2 h) {
    float2 p = __half22float2(h);
    return pack2(p.x, p.y);
}
__device__ __forceinline__ void barA() { asm volatile("bar.sync 1, 256;" ::: "memory"); }
__device__ __forceinline__ void cluster_sync() {
    asm volatile("barrier.cluster.arrive.aligned;" ::: "memory");
    asm volatile("barrier.cluster.wait.aligned;" ::: "memory");
}
__device__ __forceinline__ unsigned int smem_u32(const void* p) {
    unsigned int a;
    asm("{ .reg .u64 t; cvta.to.shared.u64 t, %1; cvt.u32.u64 %0, t; }" : "=r"(a) : "l"(p));
    return a;
}
__device__ __forceinline__ unsigned int mapa_u32(unsigned int a, unsigned int rank) {
    unsigned int r;
    asm("mapa.shared::cluster.u32 %0, %1, %2;" : "=r"(r) : "r"(a), "r"(rank));
    return r;
}
__device__ __forceinline__ void stc_f32(unsigned int a, float v) {
    asm volatile("st.shared::cluster.f32 [%0], %1;" :: "r"(a), "f"(v) : "memory");
}

__global__ void __launch_bounds__(256) convert_weights_kernel(
    const float* __restrict__ W1, const float* __restrict__ Whh,
    const float* __restrict__ Wih)
{
    int i = blockIdx.x * 256 + threadIdx.x;
    if (i < D_ * E_) {
        int d = i >> 8, c = i & 255;
        g_whc[i] = __floats2half2_rn(W1[d * E_ + c], W1[(D_ + d) * E_ + c]);
    }
    if (i < D_ * 4 * D_) g_whh[i] = __float2half_rn(Whh[i]);
    if (i < O_ * 4 * D_) g_wih[i] = __float2half_rn(Wih[i]);
}

// enc_proj = x[b] @ We -> g_ep16 (one CTA per batch)
__global__ void __launch_bounds__(512) encproj_kernel(
    const float* __restrict__ x, const float* __restrict__ W1)
{
    extern __shared__ char sm[];
    __half* xs = (__half*)sm;
    const int b = blockIdx.x, t = threadIdx.x;
    const int r = t >> 6, j = t & 63;

    const float* xb = x + (size_t)b * S_ * E_;
    for (int i = t; i < S_ * E_; i += 512) xs[i] = __float2half_rn(xb[i]);
    __syncthreads();

    const float4* We4 = (const float4*)(W1 + 2 * D_ * E_);
    __half* epb = g_ep16 + (size_t)b * S_ * E_;
    for (int s0 = 16 * r; s0 < 16 * r + 16; s0 += 8) {
        float4 acc[8];
        #pragma unroll
        for (int q = 0; q < 8; q++) acc[q] = make_float4(0.f, 0.f, 0.f, 0.f);
        for (int e = 0; e < E_; e++) {
            float4 wv = We4[e * 64 + j];
            #pragma unroll
            for (int q = 0; q < 8; q++) {
                float xv = __half2float(xs[(s0 + q) * E_ + e]);
                acc[q].x = fmaf(xv, wv.x, acc[q].x);
                acc[q].y = fmaf(xv, wv.y, acc[q].y);
                acc[q].z = fmaf(xv, wv.z, acc[q].z);
                acc[q].w = fmaf(xv, wv.w, acc[q].w);
            }
        }
        #pragma unroll
        for (int q = 0; q < 8; q++) {
            __half2* rowp = (__half2*)(epb + (size_t)(s0 + q) * E_);
            rowp[2 * j]     = __floats2half2_rn(acc[q].x, acc[q].y);
            rowp[2 * j + 1] = __floats2half2_rn(acc[q].z, acc[q].w);
        }
    }
}

__global__ void __launch_bounds__(NT, 1) __cluster_dims__(2, 1, 1)
attn_decoder_kernel(
    const float* __restrict__ x, const float* __restrict__ yh,
    const float* __restrict__ h0, const float* __restrict__ c0,
    const float* __restrict__ b1, const float* __restrict__ w2,
    const float* __restrict__ b2, const float* __restrict__ bih,
    const float* __restrict__ bhh, const float* __restrict__ fcW,
    const float* __restrict__ fcb)
{
    extern __shared__ char smraw[];
    __half* ep_sm = (__half*)(smraw + OFF_EP);
    float*  XF    = (float*)(smraw + OFF_XF);
    float*  YF    = (float*)(smraw + OFF_YF);
    __half* x16   = (__half*)(smraw + OFF_SCR);   // prologue only
    float*  pwhc  = (float*)(smraw + OFF_PWHC);
    float*  pwhh  = (float*)(smraw + OFF_PWHH);
    float*  gfin  = (float*)(smraw + OFF_GFIN);
    float*  partA = (float*)(smraw + OFF_PA);
    float*  hsm   = (float*)(smraw + OFF_H);      // [2][256] both batches
    float*  csm   = (float*)(smraw + OFF_C);
    float*  hcsm  = (float*)(smraw + OFF_HC);     // own batch full hc
    float*  sc    = (float*)(smraw + OFF_SC);
    float*  ytl2  = (float*)(smraw + OFF_YT);     // [2][64]
    float*  gb    = (float*)(smraw + OFF_GB);
    float*  w2s   = (float*)(smraw + OFF_W2);
    float*  b1s   = (float*)(smraw + OFF_B1);

    const int myb  = blockIdx.x;
    const int rho  = blockIdx.x & 1;          // cluster rank
    const int pb   = blockIdx.x & ~1;         // pair base batch
    const int t    = threadIdx.x;
    const int lane = t & 31, w = t >> 5;

    const unsigned int peer_base = mapa_u32(smem_u32(smraw), 1 - rho);

    // ---- prologue ----
    const float* xb = x + (size_t)myb * S_ * E_;
    for (int i = t; i < S_ * E_; i += NT) x16[i] = __float2half_rn(xb[i]);
    {   // load ep16 -> SMEM
        const uint4* eps = (const uint4*)(g_ep16 + (size_t)myb * S_ * E_);
        uint4* epd = (uint4*)ep_sm;
        for (int i = t; i < S_ * E_ / 8; i += NT) epd[i] = eps[i];
    }
    {   // h,c for BOTH batches of the pair
        int bt = t >> 8, d = t & 255;
        hsm[t] = h0[(pb + bt) * D_ + d];
        csm[t] = c0[(pb + bt) * D_ + d];
    }
    if (t < 256) {
        w2s[t] = w2[t];
        b1s[t] = b1[t];
        float4 a  = ((const float4*)bih)[t];
        float4 c4 = ((const float4*)bhh)[t];
        ((float4*)gb)[t] = make_float4(a.x + c4.x, a.y + c4.y, a.z + c4.z, a.w + c4.w);
    }
    const float b2c = b2[0];
    __syncthreads();

    // XF[s][j] = sum_e x[s][e]*fcW[e][j]
    {
        const int sB = t >> 6, j = t & 63;
        float acc[16];
        #pragma unroll
        for (int si = 0; si < 16; si++) acc[si] = 0.f;
        for (int e = 0; e < E_; e++) {
            float wv = fcW[e * 64 + j];
            #pragma unroll
            for (int si = 0; si < 16; si++)
                acc[si] = fmaf(__half2float(x16[(16 * sB + si) * E_ + e]), wv, acc[si]);
        }
        #pragma unroll
        for (int si = 0; si < 16; si++) XF[(16 * sB + si) * 64 + j] = acc[si];
    }
    // YF[t][j] = fcb[j] + sum_o yh[myb][t][o]*fcW[256+o][j]
    {
        const int tB = t >> 6, j = t & 63;
        float acc[16];
        #pragma unroll
        for (int si = 0; si < 16; si++) acc[si] = 0.f;
        const float* yhb = yh + (size_t)myb * S_ * O_;
        for (int o = 0; o < O_; o++) {
            float wv = fcW[(E_ + o) * 64 + j];
            #pragma unroll
            for (int si = 0; si < 16; si++)
                acc[si] = fmaf(yhb[(16 * tB + si) * O_ + o], wv, acc[si]);
        }
        float fb = fcb[j];
        #pragma unroll
        for (int si = 0; si < 16; si++) YF[(16 * tB + si) * 64 + j] = acc[si] + fb;
    }
    __syncthreads();   // x16 region now free -> partials
    cluster_sync();    // both CTAs initialized before any peer writes

    const uint4* whc4 = (const uint4*)g_whc;   // row d: 64 uint4
    const uint4* whh4 = (const uint4*)g_whh;   // row k: 128 uint4
    const unsigned int* wihu = (const unsigned int*)g_wih;   // row k: 512 half2

    for (int step = 0; step < S_; step++) {
        // ===== Phase 1: whc partials (FFMA2-packed), own-half cols, both batches =====
        {
            const int ks = t >> 5, cu = t & 31;
            const int d0 = 16 * ks;
            ull A0[4], A1[4];   // per col: packed (sum h*Wh, sum c*Wc)
            const ull z = pack2(0.f, 0.f);
            #pragma unroll
            for (int i = 0; i < 4; i++) { A0[i] = z; A1[i] = z; }
            #pragma unroll
            for (int kk = 0; kk < 16; kk += 8) {
                uint4 v[8];
                #pragma unroll
                for (int q = 0; q < 8; q++)
                    v[q] = whc4[(d0 + kk + q) * 64 + rho * 32 + cu];
                #pragma unroll
                for (int q = 0; q < 8; q++) {
                    int d = d0 + kk + q;
                    ull hc0 = pack2(hsm[d], csm[d]);
                    ull hc1 = pack2(hsm[256 + d], csm[256 + d]);
                    #pragma unroll
                    for (int k = 0; k < 4; k++) {
                        ull wp = h2_to_ull(((const __half2*)&v[q])[k]);
                        A0[k] = fma2(hc0, wp, A0[k]);
                        A1[k] = fma2(hc1, wp, A1[k]);
                    }
                }
            }
            float a0[4], a1[4];
            #pragma unroll
            for (int k = 0; k < 4; k++) {
                float2 f0 = unpack2(A0[k]);
                float2 f1 = unpack2(A1[k]);
                a0[k] = f0.x + f0.y;
                a1[k] = f1.x + f1.y;
            }
            ((float4*)(pwhc + (ks * 2 + 0) * 128))[cu] = make_float4(a0[0], a0[1], a0[2], a0[3]);
            ((float4*)(pwhc + (ks * 2 + 1) * 128))[cu] = make_float4(a1[0], a1[1], a1[2], a1[3]);
        }
        __syncthreads();
        if (t < 256) {   // reduce + route hc pieces
            const int bt = t >> 7, cl = t & 127;
            float v = b1s[128 * rho + cl];
            #pragma unroll
            for (int ks = 0; ks < 16; ks++) v += pwhc[(ks * 2 + bt) * 128 + cl];
            if (bt == rho) hcsm[128 * rho + cl] = v;
            else stc_f32(peer_base + OFF_HC + 4 * (128 * rho + cl), v);
        }
        cluster_sync();   // #1 — hc complete in every CTA

        if (t < 256) {
            // ===== Phase 2A: scores -> softmax -> ytl (own batch) =====
            float hcr[8], w2r[8];
            *(float4*)&hcr[0] = *(float4*)(hcsm + 8 * lane);
            *(float4*)&hcr[4] = *(float4*)(hcsm + 8 * lane + 4);
            *(float4*)&w2r[0] = *(float4*)(w2s + 8 * lane);
            *(float4*)&w2r[4] = *(float4*)(w2s + 8 * lane + 4);
            #pragma unroll 2
            for (int si = 0; si < 16; si++) {
                int s = 16 * w + si;
                uint4 u = ((const uint4*)ep_sm)[(s << 5) + lane];
                float sum = 0.f;
                #pragma unroll
                for (int k = 0; k < 4; k++) {
                    float2 p = __half22float2(((const __half2*)&u)[k]);
                    sum = fmaf(tanh_a(p.x + hcr[2 * k]),     w2r[2 * k],     sum);
                    sum = fmaf(tanh_a(p.y + hcr[2 * k + 1]), w2r[2 * k + 1], sum);
                }
                #pragma unroll
                for (int off = 16; off; off >>= 1)
                    sum += __shfl_xor_sync(0xffffffffu, sum, off);
                if (lane == 0) sc[s] = sum + b2c;
            }
            barA();
            if (w == 0) {
                float v0 = sc[lane], v1 = sc[32 + lane], v2 = sc[64 + lane], v3 = sc[96 + lane];
                float m = fmaxf(fmaxf(v0, v1), fmaxf(v2, v3));
                #pragma unroll
                for (int off = 16; off; off >>= 1)
                    m = fmaxf(m, __shfl_xor_sync(0xffffffffu, m, off));
                float e0 = __expf(v0 - m), e1 = __expf(v1 - m);
                float e2 = __expf(v2 - m), e3 = __expf(v3 - m);
                float s2 = e0 + e1 + e2 + e3;
                #pragma unroll
                for (int off = 16; off; off >>= 1)
                    s2 += __shfl_xor_sync(0xffffffffu, s2, off);
                float inv = __fdividef(1.f, s2);
                sc[lane]      = e0 * inv;
                sc[32 + lane] = e1 * inv;
                sc[64 + lane] = e2 * inv;
                sc[96 + lane] = e3 * inv;
            }
            barA();
            {   // ytl = alpha^T XF + YF[step]
                const int sq = t >> 6, j = t & 63;
                float acc = 0.f;
                #pragma unroll 8
                for (int s = 32 * sq; s < 32 * sq + 32; s++)
                    acc = fmaf(sc[s], XF[s * 64 + j], acc);
                partA[t] = acc;
            }
            barA();
            if (t < O_) {
                float v = YF[step * 64 + t] + partA[t] + partA[64 + t]
                        + partA[128 + t] + partA[192 + t];
                ytl2[rho * 64 + t] = v;
                stc_f32(peer_base + OFF_YT + 4 * (rho * 64 + t), v);
            }
        } else {
            // ===== Phase 2B: Whh own-half cols (FFMA2 col-pairs), both batches =====
            const int tb  = t - 256;
            const int khB = tb >> 6, cu2 = tb & 63;
            const int q   = cu2 >> 4, c16 = cu2 & 15;
            const int colu = q * 32 + rho * 16 + c16;
            ull A0[4], A1[4];   // col pairs (2k, 2k+1)
            const ull z = pack2(0.f, 0.f);
            #pragma unroll
            for (int i = 0; i < 4; i++) { A0[i] = z; A1[i] = z; }
            const int base = 64 * khB;
            #pragma unroll 2
            for (int k0 = 0; k0 < 64; k0 += 8) {
                uint4 v[8];
                #pragma unroll
                for (int qq = 0; qq < 8; qq++)
                    v[qq] = whh4[(base + k0 + qq) * 128 + colu];
                #pragma unroll
                for (int qq = 0; qq < 8; qq++) {
                    float h0v = hsm[base + k0 + qq];
                    float h1v = hsm[256 + base + k0 + qq];
                    ull hh0 = pack2(h0v, h0v);
                    ull hh1 = pack2(h1v, h1v);
                    #pragma unroll
                    for (int k = 0; k < 4; k++) {
                        ull wp = h2_to_ull(((const __half2*)&v[qq])[k]);
                        A0[k] = fma2(hh0, wp, A0[k]);
                        A1[k] = fma2(hh1, wp, A1[k]);
                    }
                }
            }
            float a0[8], a1[8];
            #pragma unroll
            for (int k = 0; k < 4; k++) {
                float2 f0 = unpack2(A0[k]);
                float2 f1 = unpack2(A1[k]);
                a0[2 * k] = f0.x; a0[2 * k + 1] = f0.y;
                a1[2 * k] = f1.x; a1[2 * k + 1] = f1.y;
            }
            float* d0p = pwhh + (khB * 2 + 0) * 512 + q * 128 + c16 * 8;
            float* d1p = pwhh + (khB * 2 + 1) * 512 + q * 128 + c16 * 8;
            ((float4*)d0p)[0] = make_float4(a0[0], a0[1], a0[2], a0[3]);
            ((float4*)d0p)[1] = make_float4(a0[4], a0[5], a0[6], a0[7]);
            ((float4*)d1p)[0] = make_float4(a1[0], a1[1], a1[2], a1[3]);
            ((float4*)d1p)[1] = make_float4(a1[4], a1[5], a1[6], a1[7]);
        }
        cluster_sync();   // #2 — ytl both batches + Whh partials ready

        // ===== Phase 3: wih (FFMA2) + gate assemble (threads 0..255) =====
        if (t < 256) {
            const int q = t >> 6, p = t & 63;
            const int cidx  = q * 128 + 64 * rho + p;   // half2 col in wih row
            const int hc512 = q * 128 + 2 * p;
            ull C0 = pack2(0.f, 0.f), C1 = pack2(0.f, 0.f);
            #pragma unroll 2
            for (int k0 = 0; k0 < 64; k0 += 8) {
                unsigned int u[8];
                #pragma unroll
                for (int qq = 0; qq < 8; qq++) u[qq] = wihu[(k0 + qq) * 512 + cidx];
                #pragma unroll
                for (int qq = 0; qq < 8; qq++) {
                    float y0 = ytl2[k0 + qq], y1 = ytl2[64 + k0 + qq];
                    ull wp = h2_to_ull(*(__half2*)&u[qq]);
                    C0 = fma2(pack2(y0, y0), wp, C0);
                    C1 = fma2(pack2(y1, y1), wp, C1);
                }
            }
            float2 acc0 = unpack2(C0), acc1 = unpack2(C1);
            #pragma unroll
            for (int ks = 0; ks < 4; ks++) {
                acc0.x += pwhh[(ks * 2 + 0) * 512 + hc512];
                acc0.y += pwhh[(ks * 2 + 0) * 512 + hc512 + 1];
                acc1.x += pwhh[(ks * 2 + 1) * 512 + hc512];
                acc1.y += pwhh[(ks * 2 + 1) * 512 + hc512 + 1];
            }
            float2 gbv = *(const float2*)(gb + q * 256 + 128 * rho + 2 * p);
            acc0.x += gbv.x; acc0.y += gbv.y;
            acc1.x += gbv.x; acc1.y += gbv.y;
            *(float2*)(gfin + hc512)       = acc0;
            *(float2*)(gfin + 512 + hc512) = acc1;
        }
        __syncthreads();
        if (t < 256) {   // pointwise: own-half d, both batches; export to peer
            const int bt = t >> 7, dl = t & 127;
            const int d = 128 * rho + dl;
            const float* g = gfin + bt * 512;
            float gi = g[dl], gf = g[128 + dl], gg = g[256 + dl], go = g[384 + dl];
            float cv = csm[bt * 256 + d];
            float cn = fmaf(sigm_f(gf), cv, sigm_f(gi) * tanh_f(gg));
            float hn = sigm_f(go) * tanh_f(cn);
            hsm[bt * 256 + d] = hn;
            csm[bt * 256 + d] = cn;
            stc_f32(peer_base + OFF_H + 4 * (bt * 256 + d), hn);
            stc_f32(peer_base + OFF_C + 4 * (bt * 256 + d), cn);
        }
        cluster_sync();   // #3 — full h,c everywhere
    }

    // epilogue: h_T + context_T for own batch (context from global x, final alpha)
    if (t < 256) {
        float acc = 0.f;
        const float* xg = x + (size_t)myb * S_ * E_;
        #pragma unroll 4
        for (int s = 0; s < S_; s++)
            acc = fmaf(sc[s], xg[s * E_ + t], acc);
        g_hctx[myb * 512 + t]       = hsm[rho * 256 + t];
        g_hctx[myb * 512 + 256 + t] = acc;
    }
    cluster_sync();   // no CTA exits while peer may still write our SMEM
}

// out[128, 8192] = g_hctx[128,512] @ fc_out_W[512,8192] + b
__global__ void __launch_bounds__(256, 1) fcout_kernel(
    const float* __restrict__ W, const float* __restrict__ bias,
    float* __restrict__ out)
{
    __shared__ float As[32][128];
    __shared__ float Ws[32][64];
    const int n0 = blockIdx.x * 64;
    const int t  = threadIdx.x;
    const int tx = t & 7, ty = t >> 3;

    float bv[8];
    #pragma unroll
    for (int jj = 0; jj < 8; jj++) bv[jj] = bias[n0 + 8 * tx + jj];

    float acc[4][8];
    #pragma unroll
    for (int i = 0; i < 4; i++)
        #pragma unroll
        for (int jj = 0; jj < 8; jj++) acc[i][jj] = 0.f;

    for (int k0 = 0; k0 < 512; k0 += 32) {
        {
            int q    = t & 7;
            int row0 = t >> 3;
            #pragma unroll
            for (int i = 0; i < 4; i++) {
                int rr = row0 + 32 * i;
                float4 v = *(const float4*)(g_hctx + rr * 512 + k0 + 4 * q);
                As[4 * q + 0][rr] = v.x;
                As[4 * q + 1][rr] = v.y;
                As[4 * q + 2][rr] = v.z;
                As[4 * q + 3][rr] = v.w;
            }
            int nq  = t & 15;
            int kk0 = t >> 4;
            #pragma unroll
            for (int i = 0; i < 2; i++) {
                int kk = kk0 + 16 * i;
                float4 v = *(const float4*)(W + (size_t)(k0 + kk) * 8192 + n0 + 4 * nq);
                *(float4*)(&Ws[kk][4 * nq]) = v;
            }
        }
        __syncthreads();
        #pragma unroll 8
        for (int kk = 0; kk < 32; kk++) {
            float a[4], wv[8];
            #pragma unroll
            for (int i = 0; i < 4; i++) a[i] = As[kk][4 * ty + i];
            #pragma unroll
            for (int jj = 0; jj < 8; jj++) wv[jj] = Ws[kk][8 * tx + jj];
            #pragma unroll
            for (int i = 0; i < 4; i++)
                #pragma unroll
                for (int jj = 0; jj < 8; jj++)
                    acc[i][jj] = fmaf(a[i], wv[jj], acc[i][jj]);
        }
        __syncthreads();
    }
    #pragma unroll
    for (int i = 0; i < 4; i++) {
        int bb = 4 * ty + i;
        #pragma unroll
        for (int jj = 0; jj < 8; jj++)
            out[(size_t)bb * 8192 + n0 + 8 * tx + jj] = acc[i][jj] + bv[jj];
    }
}

extern "C" void kernel_launch(void* const* d_in, const int* in_sizes, int n_in,
                              void* d_out, int out_size)
{
    const float* x   = (const float*)d_in[0];
    const float* yh  = (const float*)d_in[1];
    const float* h0  = (const float*)d_in[2];
    const float* c0  = (const float*)d_in[3];
    const float* W1  = (const float*)d_in[4];
    const float* b1  = (const float*)d_in[5];
    const float* w2  = (const float*)d_in[6];
    const float* b2  = (const float*)d_in[7];
    const float* Wih = (const float*)d_in[8];
    const float* Whh = (const float*)d_in[9];
    const float* bih = (const float*)d_in[10];
    const float* bhh = (const float*)d_in[11];
    const float* fcW = (const float*)d_in[12];
    const float* fcb = (const float*)d_in[13];
    const float* foW = (const float*)d_in[14];
    const float* fob = (const float*)d_in[15];

    convert_weights_kernel<<<(D_ * 4 * D_ + 255) / 256, 256>>>(W1, Whh, Wih);

    cudaFuncSetAttribute(encproj_kernel,
                         cudaFuncAttributeMaxDynamicSharedMemorySize, S_ * E_ * 2);
    encproj_kernel<<<B_, 512, S_ * E_ * 2>>>(x, W1);

    cudaFuncSetAttribute(attn_decoder_kernel,
                         cudaFuncAttributeMaxDynamicSharedMemorySize, SMEM_BYTES);
    attn_decoder_kernel<<<B_, NT, SMEM_BYTES>>>(x, yh, h0, c0, b1, w2, b2,
                                                bih, bhh, fcW, fcb);
    fcout_kernel<<<128, 256>>>(foW, fob, (float*)d_out);
}